// round 5
// baseline (speedup 1.0000x reference)
#include <cuda_runtime.h>

// Problem constants (fixed by the reference)
constexpr int cN   = 50000;
constexpr int cE   = 400000;
constexpr int cR   = 3;
constexpr int cH   = 3;
constexpr int cIN  = 128;
constexpr int cHID = 64;
constexpr int cOUT = 64;
constexpr int cC   = 16;
constexpr int cB   = 8;
constexpr int cF2  = cH * cHID;   // 192
constexpr int cM   = cN * cH;     // 150000 rows for conv2
constexpr int cRN  = cR * cN;     // 150000
constexpr int cRE  = cR * cE;     // 1.2M
constexpr int SCAN_NB = (cRN + 1023) / 1024;  // 147

// ------------------------- device scratch (static, no alloc) -------------------------
__device__ int      g_outdeg[cRN];
__device__ int      g_indeg[cRN];
__device__ float    g_ns[cRN];
__device__ float    g_nd[cRN];
__device__ int      g_off[cRN + 1];
__device__ int      g_cursor[cRN];
__device__ int      g_bsum[256];
__device__ int      g_esrc[cRE];
__device__ float    g_xW[cRN * cHID];
__device__ float    g_h1[cN * cHID];
__device__ float    g_f[(size_t)cRN * cF2];
__device__ float    g_el4[cRN * 4];                 // padded: [idx*4 + h], h<3
__device__ float    g_er4[cRN * 4];
__device__ float    g_gat[cN * cF2];
__device__ float    g_xW2[(size_t)cR * cM * cOUT];
__device__ float    g_acc2[cM * cOUT];
__device__ float    g_pool[cB * cF2];
__device__ float    g_cnt[cB];

__device__ __forceinline__ float sigmoidf_(float v) { return 1.f / (1.f + __expf(-v)); }

// ------------------------- init -------------------------
__global__ void k_init0() {
    int i = blockIdx.x * blockDim.x + threadIdx.x;
    if (i < cRN) { g_outdeg[i] = 0; g_indeg[i] = 0; }
    if (i < cB * cF2) g_pool[i] = 0.f;
    if (i < cB)       g_cnt[i] = 0.f;
}

// ------------------------- degrees -------------------------
__global__ void k_deg(const int* __restrict__ src, const int* __restrict__ dst) {
    int i = blockIdx.x * blockDim.x + threadIdx.x;
    if (i >= cRE) return;
    int r = i / cE;
    atomicAdd(&g_outdeg[r * cN + src[i]], 1);
    atomicAdd(&g_indeg[r * cN + dst[i]], 1);
}
__global__ void k_norm() {
    int i = blockIdx.x * blockDim.x + threadIdx.x;
    if (i >= cRN) return;
    g_ns[i] = rsqrtf(fmaxf((float)g_outdeg[i], 1.f));
    g_nd[i] = rsqrtf(fmaxf((float)g_indeg[i], 1.f));
}

// ------------------------- exclusive scan of indeg -> offsets -------------------------
__global__ void k_scanA() {
    __shared__ int wsum[8];
    int tid = threadIdx.x, lane = tid & 31, wid = tid >> 5;
    int idx0 = blockIdx.x * 1024 + tid * 4;
    int v[4]; int s = 0;
#pragma unroll
    for (int k = 0; k < 4; k++) {
        int i = idx0 + k;
        int x = (i < cRN) ? g_indeg[i] : 0;
        v[k] = s; s += x;
    }
    int incl = s;
#pragma unroll
    for (int o = 1; o < 32; o <<= 1) {
        int t = __shfl_up_sync(0xffffffffu, incl, o);
        if (lane >= o) incl += t;
    }
    int excl = incl - s;
    if (lane == 31) wsum[wid] = incl;
    __syncthreads();
    if (tid == 0) {
        int a = 0;
#pragma unroll
        for (int w = 0; w < 8; w++) { int t = wsum[w]; wsum[w] = a; a += t; }
        g_bsum[blockIdx.x] = a;
    }
    __syncthreads();
    int base = wsum[wid] + excl;
#pragma unroll
    for (int k = 0; k < 4; k++) {
        int i = idx0 + k;
        if (i < cRN) g_off[i] = base + v[k];
    }
}
__global__ void k_scanB() {
    __shared__ int wsum[8];
    int tid = threadIdx.x, lane = tid & 31, wid = tid >> 5;
    int v = (tid < SCAN_NB) ? g_bsum[tid] : 0;
    int incl = v;
#pragma unroll
    for (int o = 1; o < 32; o <<= 1) {
        int t = __shfl_up_sync(0xffffffffu, incl, o);
        if (lane >= o) incl += t;
    }
    if (lane == 31) wsum[wid] = incl;
    __syncthreads();
    if (tid == 0) {
        int a = 0;
#pragma unroll
        for (int w = 0; w < 8; w++) { int t = wsum[w]; wsum[w] = a; a += t; }
    }
    __syncthreads();
    if (tid < SCAN_NB) g_bsum[tid] = wsum[wid] + incl - v;
}
__global__ void k_scanC() {
    int i = blockIdx.x * blockDim.x + threadIdx.x;
    if (i >= cRN) return;
    int o = g_off[i] + g_bsum[i >> 10];
    g_off[i] = o;
    g_cursor[i] = o;
    if (i == 0) g_off[cRN] = cRE;
}
__global__ void k_fill(const int* __restrict__ src, const int* __restrict__ dst) {
    int i = blockIdx.x * blockDim.x + threadIdx.x;
    if (i >= cRE) return;
    int r = i / cE;
    int pos = atomicAdd(&g_cursor[r * cN + dst[i]], 1);
    g_esrc[pos] = src[i];
}

// ------------------------- GEMM: C[rows,64·gz] = A[rows,K] @ B[r][K,·]  -------------------------
// block: 256 threads, 64 rows x 64 cols tile; thread = 1 row x 16 cols (8 f32x2 acc)
template<int K>
__global__ void __launch_bounds__(256) k_gemm(
    const float* __restrict__ A, int ldA,
    const float* __restrict__ B, int ldB, size_t sBrel,
    float* __restrict__ C, int ldC, size_t sCrel,
    int rows)
{
    extern __shared__ float sm[];
    constexpr int SAS = K + 4;           // stride ≡ 4 (mod 32) -> conflict-free broadcast reads
    float* sA = sm;                      // [64][SAS]
    float* sB = sm + 64 * SAS;           // [K][64]
    int r = blockIdx.y, ct = blockIdx.z;
    int n0 = blockIdx.x * 64;
    int tid = threadIdx.x;
    const float* Ab = A + (size_t)n0 * ldA;
    const float* Bb = B + r * sBrel + ct * 64;
    // load A tile (64 x K), coalesced float4
    for (int i = tid; i < 64 * (K / 4); i += 256) {
        int row = i / (K / 4), c4 = i % (K / 4);
        float4 v = (n0 + row < rows)
            ? __ldg((const float4*)(Ab + (size_t)row * ldA) + c4)
            : make_float4(0.f, 0.f, 0.f, 0.f);
        *(float4*)(sA + row * SAS + c4 * 4) = v;
    }
    // load B tile (K x 64), coalesced float4
    for (int i = tid; i < K * 16; i += 256) {
        int k = i / 16, c4 = i % 16;
        float4 v = __ldg((const float4*)(Bb + (size_t)k * ldB) + c4);
        *(float4*)(sB + k * 64 + c4 * 4) = v;
    }
    __syncthreads();

    int row = tid >> 2, colg = (tid & 3) * 16;
    unsigned long long acc[8];
#pragma unroll
    for (int j = 0; j < 8; j++) acc[j] = 0ull;
    const float* sAr = sA + row * SAS;
#pragma unroll 4
    for (int k = 0; k < K; k++) {
        float a = sAr[k];
        unsigned long long aa;
        asm("mov.b64 %0, {%1, %1};" : "=l"(aa) : "f"(a));
        const unsigned long long* bp = (const unsigned long long*)(sB + k * 64 + colg);
#pragma unroll
        for (int j = 0; j < 8; j++)
            asm("fma.rn.f32x2 %0, %1, %2, %0;" : "+l"(acc[j]) : "l"(aa), "l"(bp[j]));
    }
    int n = n0 + row;
    if (n < rows) {
        float* Cp = C + r * sCrel + (size_t)n * ldC + ct * 64 + colg;
#pragma unroll
        for (int j = 0; j < 8; j += 2) {
            float ax, ay, bx, by;
            asm("mov.b64 {%0, %1}, %2;" : "=f"(ax), "=f"(ay) : "l"(acc[j]));
            asm("mov.b64 {%0, %1}, %2;" : "=f"(bx), "=f"(by) : "l"(acc[j + 1]));
            *(float4*)(Cp + j * 2) = make_float4(ax, ay, bx, by);
        }
    }
}

// ------------------------- conv1 gather + L2 normalize (fused) -------------------------
__global__ void __launch_bounds__(256) k_gath1(const float* __restrict__ b1) {
    int gw = blockIdx.x * 8 + (threadIdx.x >> 5);
    int lane = threadIdx.x & 31;
    if (gw >= cN) return;
    int n = gw;
    int p = lane * 2;
    float2 a;
    a.x = b1[p]     + b1[64 + p]     + b1[128 + p];
    a.y = b1[p + 1] + b1[64 + p + 1] + b1[128 + p + 1];
#define G1_BODY(J) { \
    int s_ = __ldg(&g_esrc[J]); \
    float sc_ = __ldg(&g_ns[r * cN + s_]) * nd; \
    float2 v_ = __ldg((const float2*)(g_xW + (size_t)(r * cN + s_) * 64) + lane); \
    a.x += sc_ * v_.x; a.y += sc_ * v_.y; }
#pragma unroll
    for (int r = 0; r < 3; r++) {
        int idx = r * cN + n;
        float nd = g_nd[idx];
        int beg = g_off[idx], end = g_off[idx + 1];
        int j = beg;
        for (; j + 4 <= end; j += 4) { G1_BODY(j) G1_BODY(j + 1) G1_BODY(j + 2) G1_BODY(j + 3) }
        for (; j < end; ++j) { G1_BODY(j) }
    }
#undef G1_BODY
    float ss = a.x * a.x + a.y * a.y;
#pragma unroll
    for (int o = 16; o; o >>= 1) ss += __shfl_xor_sync(0xffffffffu, ss, o);
    float inv = 1.f / fmaxf(sqrtf(ss), 1e-12f);
    float2* outp = (float2*)(g_h1 + (size_t)n * 64) + lane;
    outp->x = a.x * inv; outp->y = a.y * inv;
}

// ------------------------- attention logits el/er (padded to 4) -------------------------
__global__ void k_eler(const float* __restrict__ al, const float* __restrict__ ar) {
    __shared__ float sF[32 * 200];
    __shared__ float sA[2 * cF2];
    int r = blockIdx.y, n0 = blockIdx.x * 32, tid = threadIdx.x;   // 192 threads
    if (tid < cF2) { sA[tid] = al[r * cF2 + tid]; sA[cF2 + tid] = ar[r * cF2 + tid]; }
    for (int t = tid; t < 32 * 192; t += 192) {
        int row = t / 192, col = t - row * 192;
        sF[row * 200 + col] = (n0 + row < cN)
            ? g_f[((size_t)r * cN + n0 + row) * 192 + col] : 0.f;
    }
    __syncthreads();
    int node = tid / 6, slot = tid % 6, h = slot >> 1, isR = slot & 1;
    int n = n0 + node;
    if (n >= cN) return;
    const float* a  = sA + isR * cF2 + h * 64;
    const float* fr = sF + node * 200 + h * 64;
    float acc = 0.f;
#pragma unroll
    for (int k = 0; k < 64; k++) acc += fr[k] * a[k];
    float* outp = isR ? g_er4 : g_el4;
    outp[(r * cN + n) * 4 + h] = acc;
}

// ------------------------- GAT gather: shift-free softmax + weighted agg + relu -------------------------
__global__ void __launch_bounds__(256) k_ggat(const float* __restrict__ bg) {
    int gw = blockIdx.x * 8 + (threadIdx.x >> 5);
    int lane = threadIdx.x & 31;
    if (gw >= cN) return;
    int n = gw;
    int p = lane * 2;
    float2 acc0, acc1, acc2;
    acc0.x = bg[p]          + bg[192 + p]          + bg[384 + p];
    acc0.y = bg[p + 1]      + bg[192 + p + 1]      + bg[384 + p + 1];
    acc1.x = bg[64 + p]     + bg[256 + p]          + bg[448 + p];
    acc1.y = bg[64 + p + 1] + bg[256 + p + 1]      + bg[448 + p + 1];
    acc2.x = bg[128 + p]    + bg[320 + p]          + bg[512 + p];
    acc2.y = bg[128 + p + 1]+ bg[320 + p + 1]      + bg[512 + p + 1];
#define GG_BODY(J) { \
    int s_ = __ldg(&g_esrc[J]); \
    size_t sb_ = (size_t)(r * cN + s_); \
    float4 el_ = __ldg((const float4*)g_el4 + sb_); \
    float e0_ = el_.x + er.x, e1_ = el_.y + er.y, e2_ = el_.z + er.z; \
    e0_ = e0_ > 0.f ? e0_ : 0.2f * e0_; \
    e1_ = e1_ > 0.f ? e1_ : 0.2f * e1_; \
    e2_ = e2_ > 0.f ? e2_ : 0.2f * e2_; \
    float w0_ = __expf(e0_), w1_ = __expf(e1_), w2_ = __expf(e2_); \
    const float2* fr_ = (const float2*)(g_f + sb_ * 192); \
    float2 f0_ = __ldg(fr_ + lane); \
    float2 f1_ = __ldg(fr_ + 32 + lane); \
    float2 f2_ = __ldg(fr_ + 64 + lane); \
    z0 += w0_; z1 += w1_; z2 += w2_; \
    t0.x += w0_ * f0_.x; t0.y += w0_ * f0_.y; \
    t1.x += w1_ * f1_.x; t1.y += w1_ * f1_.y; \
    t2.x += w2_ * f2_.x; t2.y += w2_ * f2_.y; }
#pragma unroll
    for (int r = 0; r < 3; r++) {
        int idx = r * cN + n;
        float4 er = __ldg((const float4*)g_er4 + idx);
        float z0 = 0.f, z1 = 0.f, z2 = 0.f;
        float2 t0 = {0.f, 0.f}, t1 = {0.f, 0.f}, t2 = {0.f, 0.f};
        int beg = g_off[idx], end = g_off[idx + 1];
        int j = beg;
        for (; j + 4 <= end; j += 4) { GG_BODY(j) GG_BODY(j + 1) GG_BODY(j + 2) GG_BODY(j + 3) }
        for (; j < end; ++j) { GG_BODY(j) }
        float r0 = 1.f / (z0 + 1e-9f), r1 = 1.f / (z1 + 1e-9f), r2 = 1.f / (z2 + 1e-9f);
        acc0.x += t0.x * r0; acc0.y += t0.y * r0;
        acc1.x += t1.x * r1; acc1.y += t1.y * r1;
        acc2.x += t2.x * r2; acc2.y += t2.y * r2;
    }
#undef GG_BODY
    float2* o0 = (float2*)(g_gat + (size_t)n * 192)       + lane;
    float2* o1 = (float2*)(g_gat + (size_t)n * 192 + 64)  + lane;
    float2* o2 = (float2*)(g_gat + (size_t)n * 192 + 128) + lane;
    o0->x = fmaxf(acc0.x, 0.f); o0->y = fmaxf(acc0.y, 0.f);
    o1->x = fmaxf(acc1.x, 0.f); o1->y = fmaxf(acc1.y, 0.f);
    o2->x = fmaxf(acc2.x, 0.f); o2->y = fmaxf(acc2.y, 0.f);
}

// ------------------------- conv2 gather + sigmoid (fused) -------------------------
__global__ void __launch_bounds__(256) k_gath2(const float* __restrict__ b2) {
    int gw = blockIdx.x * 8 + (threadIdx.x >> 5);
    int lane = threadIdx.x & 31;
    if (gw >= cN) return;
    int n = gw;
    int p = lane * 2;
    float bx = b2[p]     + b2[64 + p]     + b2[128 + p];
    float by = b2[p + 1] + b2[64 + p + 1] + b2[128 + p + 1];
    float2 acc0 = {bx, by}, acc1 = {bx, by}, acc2 = {bx, by};
#define G2_BODY(J) { \
    int s_ = __ldg(&g_esrc[J]); \
    float sc_ = __ldg(&g_ns[r * cN + s_]) * nd; \
    const float2* base_ = (const float2*)(g_xW2 + ((size_t)r * cM + (size_t)s_ * 3) * 64); \
    float2 f0_ = __ldg(base_ + lane); \
    float2 f1_ = __ldg(base_ + 32 + lane); \
    float2 f2_ = __ldg(base_ + 64 + lane); \
    acc0.x += sc_ * f0_.x; acc0.y += sc_ * f0_.y; \
    acc1.x += sc_ * f1_.x; acc1.y += sc_ * f1_.y; \
    acc2.x += sc_ * f2_.x; acc2.y += sc_ * f2_.y; }
#pragma unroll
    for (int r = 0; r < 3; r++) {
        int idx = r * cN + n;
        float nd = g_nd[idx];
        int beg = g_off[idx], end = g_off[idx + 1];
        int j = beg;
        for (; j + 4 <= end; j += 4) { G2_BODY(j) G2_BODY(j + 1) G2_BODY(j + 2) G2_BODY(j + 3) }
        for (; j < end; ++j) { G2_BODY(j) }
    }
#undef G2_BODY
    float2* o0 = (float2*)(g_acc2 + (size_t)n * 192)       + lane;
    float2* o1 = (float2*)(g_acc2 + (size_t)n * 192 + 64)  + lane;
    float2* o2 = (float2*)(g_acc2 + (size_t)n * 192 + 128) + lane;
    o0->x = sigmoidf_(acc0.x); o0->y = sigmoidf_(acc0.y);
    o1->x = sigmoidf_(acc1.x); o1->y = sigmoidf_(acc1.y);
    o2->x = sigmoidf_(acc2.x); o2->y = sigmoidf_(acc2.y);
}

// ------------------------- node counts per graph -------------------------
__global__ void k_cnt(const int* __restrict__ gid) {
    int i = blockIdx.x * blockDim.x + threadIdx.x;
    if (i >= cN) return;
    int g = gid[i];
    unsigned m = __match_any_sync(__activemask(), g);
    int leader = __ffs(m) - 1;
    if ((threadIdx.x & 31) == leader)
        atomicAdd(&g_cnt[g], (float)__popc(m));
}

// ------------------------- graph pooling (acc2 already sigmoid'd) -------------------------
__global__ void k_pool(const int* __restrict__ gid) {
    int n0 = blockIdx.x * 64;
    int j  = threadIdx.x;                        // 192 threads
    int curg = -1;
    float a = 0.f;
#pragma unroll 1
    for (int m = 0; m < 64; m++) {
        int n = n0 + m;
        if (n >= cN) break;
        int g = __ldg(&gid[n]);
        float v = g_acc2[(size_t)n * 192 + j];
        if (g != curg) {
            if (curg >= 0) atomicAdd(&g_pool[curg * 192 + j], a);
            curg = g; a = 0.f;
        }
        a += v;
    }
    if (curg >= 0) atomicAdd(&g_pool[curg * 192 + j], a);
}

// ------------------------- final classifier + mean -------------------------
__global__ void k_final(const float* __restrict__ Wc, const float* __restrict__ bc,
                        float* __restrict__ out) {
    int t = threadIdx.x;                          // 384 threads
    int b = t / 48, rem = t % 48, h = rem / 16, c = rem & 15;
    float inv = 1.f / fmaxf(g_cnt[b], 1.f);
    const float* P = g_pool + (b * 3 + h) * 64;
    float dot = bc[c];
#pragma unroll
    for (int k = 0; k < 64; k++) dot += P[k] * inv * Wc[k * 16 + c];
    float sg = 1.f / (1.f + expf(-dot));
#pragma unroll
    for (int off = 8; off; off >>= 1) sg += __shfl_xor_sync(0xffffffffu, sg, off);
    if (c == 0) out[b * 3 + h] = sg * (1.f / 16.f);
}

// ------------------------- launcher -------------------------
extern "C" void kernel_launch(void* const* d_in, const int* in_sizes, int n_in,
                              void* d_out, int out_size) {
    const float* x   = (const float*)d_in[0];
    const int*   src = (const int*)  d_in[1];
    const int*   dst = (const int*)  d_in[2];
    const int*   gid = (const int*)  d_in[3];
    const float* W1  = (const float*)d_in[4];
    const float* b1  = (const float*)d_in[5];
    const float* Wg  = (const float*)d_in[6];
    const float* al  = (const float*)d_in[7];
    const float* ar  = (const float*)d_in[8];
    const float* bg  = (const float*)d_in[9];
    const float* W2  = (const float*)d_in[10];
    const float* b2  = (const float*)d_in[11];
    const float* Wc  = (const float*)d_in[12];
    const float* bc  = (const float*)d_in[13];
    float* out = (float*)d_out;

    // resolve device scratch addresses
    float *pxW, *ph1, *pf, *pgat, *pxW2;
    cudaGetSymbolAddress((void**)&pxW,  g_xW);
    cudaGetSymbolAddress((void**)&ph1,  g_h1);
    cudaGetSymbolAddress((void**)&pf,   g_f);
    cudaGetSymbolAddress((void**)&pgat, g_gat);
    cudaGetSymbolAddress((void**)&pxW2, g_xW2);

    constexpr int SM128 = (64 * (128 + 4) + 128 * 64) * 4;   // 66560 B
    constexpr int SM64  = (64 * (64 + 4)  + 64 * 64)  * 4;   // 33792 B
    static int attr_done = 0;
    if (!attr_done) {
        cudaFuncSetAttribute(k_gemm<128>, cudaFuncAttributeMaxDynamicSharedMemorySize, SM128);
        cudaFuncSetAttribute(k_gemm<64>,  cudaFuncAttributeMaxDynamicSharedMemorySize, SM64);
        attr_done = 1;
    }

    // CSR build
    k_init0<<<(cRN + 255) / 256, 256>>>();
    k_deg<<<(cRE + 255) / 256, 256>>>(src, dst);
    k_norm<<<(cRN + 255) / 256, 256>>>();
    k_scanA<<<SCAN_NB, 256>>>();
    k_scanB<<<1, 256>>>();
    k_scanC<<<(cRN + 255) / 256, 256>>>();
    k_fill<<<(cRE + 255) / 256, 256>>>(src, dst);

    // layer 1: xW[r] = x @ W1[r]
    k_gemm<128><<<dim3((cN + 63) / 64, 3, 1), 256, SM128>>>(
        x, 128, W1, 64, (size_t)128 * 64, pxW, 64, (size_t)cN * 64, cN);
    k_gath1<<<(cN + 7) / 8, 256>>>(b1);

    // GAT: f[r] = h1 @ Wg[r]  (3 col tiles of 64)
    k_gemm<64><<<dim3((cN + 63) / 64, 3, 3), 256, SM64>>>(
        ph1, 64, Wg, 192, (size_t)64 * 192, pf, 192, (size_t)cN * 192, cN);
    dim3 gE((cN + 31) / 32, cR);
    k_eler<<<gE, 192>>>(al, ar);
    k_ggat<<<(cN + 7) / 8, 256>>>(bg);

    // layer 2: xW2[r] = gat @ W2[r]   (rows = cM = N*H)
    k_gemm<64><<<dim3((cM + 63) / 64, 3, 1), 256, SM64>>>(
        pgat, 64, W2, 64, (size_t)64 * 64, pxW2, 64, (size_t)cM * 64, cM);
    k_gath2<<<(cN + 7) / 8, 256>>>(b2);

    // pooling + classifier
    k_cnt<<<(cN + 255) / 256, 256>>>(gid);
    k_pool<<<(cN + 63) / 64, 192>>>(gid);
    k_final<<<1, 384>>>(Wc, bc, out);
}

// round 6
// speedup vs baseline: 2.3266x; 2.3266x over previous
#include <cuda_runtime.h>

// Problem constants (fixed by the reference)
constexpr int cN   = 50000;
constexpr int cE   = 400000;
constexpr int cR   = 3;
constexpr int cH   = 3;
constexpr int cIN  = 128;
constexpr int cHID = 64;
constexpr int cOUT = 64;
constexpr int cC   = 16;
constexpr int cB   = 8;
constexpr int cF2  = cH * cHID;   // 192
constexpr int cM   = cN * cH;     // 150000 rows for conv2
constexpr int cRN  = cR * cN;     // 150000
constexpr int cRE  = cR * cE;     // 1.2M
constexpr int SCAN_NB = (cRN + 1023) / 1024;  // 147

// ------------------------- device scratch (static, no alloc) -------------------------
__device__ int      g_outdeg[cRN];
__device__ int      g_indeg[cRN];
__device__ float    g_ns[cRN];
__device__ float    g_nd[cRN];
__device__ int      g_off[cRN + 1];
__device__ int      g_cursor[cRN];
__device__ int      g_bsum[256];
__device__ int      g_esrc[cRE];
__device__ float    g_xW[cRN * cHID];
__device__ float    g_h1[cN * cHID];
__device__ float    g_f[(size_t)cRN * cF2];
__device__ float    g_el4[cRN * 4];                 // padded: [idx*4 + h], h<3
__device__ float    g_er4[cRN * 4];
__device__ float    g_gat[cN * cF2];
__device__ float    g_xW2[(size_t)cR * cM * cOUT];
__device__ float    g_acc2[cM * cOUT];
__device__ float    g_pool[cB * cF2];
__device__ float    g_cnt[cB];

__device__ __forceinline__ float sigmoidf_(float v) { return 1.f / (1.f + __expf(-v)); }

// ------------------------- init -------------------------
__global__ void k_init0() {
    int i = blockIdx.x * blockDim.x + threadIdx.x;
    if (i < cRN) { g_outdeg[i] = 0; g_indeg[i] = 0; }
    if (i < cB * cF2) g_pool[i] = 0.f;
    if (i < cB)       g_cnt[i] = 0.f;
}

// ------------------------- degrees -------------------------
__global__ void k_deg(const int* __restrict__ src, const int* __restrict__ dst) {
    int i = blockIdx.x * blockDim.x + threadIdx.x;
    if (i >= cRE) return;
    int r = i / cE;
    atomicAdd(&g_outdeg[r * cN + src[i]], 1);
    atomicAdd(&g_indeg[r * cN + dst[i]], 1);
}
__global__ void k_norm() {
    int i = blockIdx.x * blockDim.x + threadIdx.x;
    if (i >= cRN) return;
    g_ns[i] = rsqrtf(fmaxf((float)g_outdeg[i], 1.f));
    g_nd[i] = rsqrtf(fmaxf((float)g_indeg[i], 1.f));
}

// ------------------------- exclusive scan of indeg -> offsets -------------------------
__global__ void k_scanA() {
    __shared__ int wsum[8];
    int tid = threadIdx.x, lane = tid & 31, wid = tid >> 5;
    int idx0 = blockIdx.x * 1024 + tid * 4;
    int v[4]; int s = 0;
#pragma unroll
    for (int k = 0; k < 4; k++) {
        int i = idx0 + k;
        int x = (i < cRN) ? g_indeg[i] : 0;
        v[k] = s; s += x;
    }
    int incl = s;
#pragma unroll
    for (int o = 1; o < 32; o <<= 1) {
        int t = __shfl_up_sync(0xffffffffu, incl, o);
        if (lane >= o) incl += t;
    }
    int excl = incl - s;
    if (lane == 31) wsum[wid] = incl;
    __syncthreads();
    if (tid == 0) {
        int a = 0;
#pragma unroll
        for (int w = 0; w < 8; w++) { int t = wsum[w]; wsum[w] = a; a += t; }
        g_bsum[blockIdx.x] = a;
    }
    __syncthreads();
    int base = wsum[wid] + excl;
#pragma unroll
    for (int k = 0; k < 4; k++) {
        int i = idx0 + k;
        if (i < cRN) g_off[i] = base + v[k];
    }
}
__global__ void k_scanB() {
    __shared__ int wsum[8];
    int tid = threadIdx.x, lane = tid & 31, wid = tid >> 5;
    int v = (tid < SCAN_NB) ? g_bsum[tid] : 0;
    int incl = v;
#pragma unroll
    for (int o = 1; o < 32; o <<= 1) {
        int t = __shfl_up_sync(0xffffffffu, incl, o);
        if (lane >= o) incl += t;
    }
    if (lane == 31) wsum[wid] = incl;
    __syncthreads();
    if (tid == 0) {
        int a = 0;
#pragma unroll
        for (int w = 0; w < 8; w++) { int t = wsum[w]; wsum[w] = a; a += t; }
    }
    __syncthreads();
    if (tid < SCAN_NB) g_bsum[tid] = wsum[wid] + incl - v;
}
__global__ void k_scanC() {
    int i = blockIdx.x * blockDim.x + threadIdx.x;
    if (i >= cRN) return;
    int o = g_off[i] + g_bsum[i >> 10];
    g_off[i] = o;
    g_cursor[i] = o;
    if (i == 0) g_off[cRN] = cRE;
}
__global__ void k_fill(const int* __restrict__ src, const int* __restrict__ dst) {
    int i = blockIdx.x * blockDim.x + threadIdx.x;
    if (i >= cRE) return;
    int r = i / cE;
    int pos = atomicAdd(&g_cursor[r * cN + dst[i]], 1);
    g_esrc[pos] = src[i];
}

// ------------------------- GEMM: C[rows, 64·gz] = A[rows,K] @ B[r][K,·] -------------------------
// 256 threads, 64x64 tile, thread = 4 rows x 4 cols register block (plain FFMA).
template<int K>
__global__ void __launch_bounds__(256) k_gemm(
    const float* __restrict__ A, int ldA,
    const float* __restrict__ B, int ldB, size_t sBrel,
    float* __restrict__ C, int ldC, size_t sCrel,
    int rows)
{
    extern __shared__ float sm[];
    constexpr int SAS = K + 4;           // row stride ≡ 4 (mod 32)
    float* sA = sm;                      // [64][SAS]
    float* sB = sm + 64 * SAS;           // [K][64]
    int r = blockIdx.y, ct = blockIdx.z;
    int n0 = blockIdx.x * 64;
    int tid = threadIdx.x;
    const float* Ab = A + (size_t)n0 * ldA;
    const float* Bb = B + r * sBrel + ct * 64;
    // load A tile (64 x K), coalesced float4
    for (int i = tid; i < 64 * (K / 4); i += 256) {
        int row = i / (K / 4), c4 = i % (K / 4);
        float4 v = (n0 + row < rows)
            ? __ldg((const float4*)(Ab + (size_t)row * ldA) + c4)
            : make_float4(0.f, 0.f, 0.f, 0.f);
        *(float4*)(sA + row * SAS + c4 * 4) = v;
    }
    // load B tile (K x 64), coalesced float4
    for (int i = tid; i < K * 16; i += 256) {
        int k = i / 16, c4 = i % 16;
        float4 v = __ldg((const float4*)(Bb + (size_t)k * ldB) + c4);
        *(float4*)(sB + k * 64 + c4 * 4) = v;
    }
    __syncthreads();

    int ty = tid >> 4, tx = tid & 15;            // 16x16 thread grid
    int row0 = ty * 4, col0 = tx * 4;
    float acc[4][4];
#pragma unroll
    for (int i = 0; i < 4; i++)
#pragma unroll
        for (int j = 0; j < 4; j++) acc[i][j] = 0.f;

    const float* a0 = sA + (row0 + 0) * SAS;
    const float* a1 = sA + (row0 + 1) * SAS;
    const float* a2 = sA + (row0 + 2) * SAS;
    const float* a3 = sA + (row0 + 3) * SAS;
#pragma unroll 2
    for (int k = 0; k < K; k++) {
        float4 b = *(const float4*)(sB + k * 64 + col0);
        float v0 = a0[k], v1 = a1[k], v2 = a2[k], v3 = a3[k];
        acc[0][0] += v0 * b.x; acc[0][1] += v0 * b.y; acc[0][2] += v0 * b.z; acc[0][3] += v0 * b.w;
        acc[1][0] += v1 * b.x; acc[1][1] += v1 * b.y; acc[1][2] += v1 * b.z; acc[1][3] += v1 * b.w;
        acc[2][0] += v2 * b.x; acc[2][1] += v2 * b.y; acc[2][2] += v2 * b.z; acc[2][3] += v2 * b.w;
        acc[3][0] += v3 * b.x; acc[3][1] += v3 * b.y; acc[3][2] += v3 * b.z; acc[3][3] += v3 * b.w;
    }
#pragma unroll
    for (int i = 0; i < 4; i++) {
        int n = n0 + row0 + i;
        if (n < rows) {
            float* Cp = C + r * sCrel + (size_t)n * ldC + ct * 64 + col0;
            *(float4*)Cp = make_float4(acc[i][0], acc[i][1], acc[i][2], acc[i][3]);
        }
    }
}

// ------------------------- conv1 gather + L2 normalize (fused) -------------------------
__global__ void __launch_bounds__(256) k_gath1(const float* __restrict__ b1) {
    int gw = blockIdx.x * 8 + (threadIdx.x >> 5);
    int lane = threadIdx.x & 31;
    if (gw >= cN) return;
    int n = gw;
    int p = lane * 2;
    float2 a;
    a.x = b1[p]     + b1[64 + p]     + b1[128 + p];
    a.y = b1[p + 1] + b1[64 + p + 1] + b1[128 + p + 1];
#define G1_BODY(J) { \
    int s_ = __ldg(&g_esrc[J]); \
    float sc_ = __ldg(&g_ns[r * cN + s_]) * nd; \
    float2 v_ = __ldg((const float2*)(g_xW + (size_t)(r * cN + s_) * 64) + lane); \
    a.x += sc_ * v_.x; a.y += sc_ * v_.y; }
#pragma unroll
    for (int r = 0; r < 3; r++) {
        int idx = r * cN + n;
        float nd = g_nd[idx];
        int beg = g_off[idx], end = g_off[idx + 1];
        int j = beg;
        for (; j + 4 <= end; j += 4) { G1_BODY(j) G1_BODY(j + 1) G1_BODY(j + 2) G1_BODY(j + 3) }
        for (; j < end; ++j) { G1_BODY(j) }
    }
#undef G1_BODY
    float ss = a.x * a.x + a.y * a.y;
#pragma unroll
    for (int o = 16; o; o >>= 1) ss += __shfl_xor_sync(0xffffffffu, ss, o);
    float inv = 1.f / fmaxf(sqrtf(ss), 1e-12f);
    float2* outp = (float2*)(g_h1 + (size_t)n * 64) + lane;
    outp->x = a.x * inv; outp->y = a.y * inv;
}

// ------------------------- attention logits el/er (padded to 4) -------------------------
__global__ void k_eler(const float* __restrict__ al, const float* __restrict__ ar) {
    __shared__ float sF[32 * 200];
    __shared__ float sA[2 * cF2];
    int r = blockIdx.y, n0 = blockIdx.x * 32, tid = threadIdx.x;   // 192 threads
    if (tid < cF2) { sA[tid] = al[r * cF2 + tid]; sA[cF2 + tid] = ar[r * cF2 + tid]; }
    for (int t = tid; t < 32 * 192; t += 192) {
        int row = t / 192, col = t - row * 192;
        sF[row * 200 + col] = (n0 + row < cN)
            ? g_f[((size_t)r * cN + n0 + row) * 192 + col] : 0.f;
    }
    __syncthreads();
    int node = tid / 6, slot = tid % 6, h = slot >> 1, isR = slot & 1;
    int n = n0 + node;
    if (n >= cN) return;
    const float* a  = sA + isR * cF2 + h * 64;
    const float* fr = sF + node * 200 + h * 64;
    float acc = 0.f;
#pragma unroll
    for (int k = 0; k < 64; k++) acc += fr[k] * a[k];
    float* outp = isR ? g_er4 : g_el4;
    outp[(r * cN + n) * 4 + h] = acc;
}

// ------------------------- GAT gather: shift-free softmax + weighted agg + relu -------------------------
__global__ void __launch_bounds__(256) k_ggat(const float* __restrict__ bg) {
    int gw = blockIdx.x * 8 + (threadIdx.x >> 5);
    int lane = threadIdx.x & 31;
    if (gw >= cN) return;
    int n = gw;
    int p = lane * 2;
    float2 acc0, acc1, acc2;
    acc0.x = bg[p]          + bg[192 + p]          + bg[384 + p];
    acc0.y = bg[p + 1]      + bg[192 + p + 1]      + bg[384 + p + 1];
    acc1.x = bg[64 + p]     + bg[256 + p]          + bg[448 + p];
    acc1.y = bg[64 + p + 1] + bg[256 + p + 1]      + bg[448 + p + 1];
    acc2.x = bg[128 + p]    + bg[320 + p]          + bg[512 + p];
    acc2.y = bg[128 + p + 1]+ bg[320 + p + 1]      + bg[512 + p + 1];
#define GG_BODY(J) { \
    int s_ = __ldg(&g_esrc[J]); \
    size_t sb_ = (size_t)(r * cN + s_); \
    float4 el_ = __ldg((const float4*)g_el4 + sb_); \
    float e0_ = el_.x + er.x, e1_ = el_.y + er.y, e2_ = el_.z + er.z; \
    e0_ = e0_ > 0.f ? e0_ : 0.2f * e0_; \
    e1_ = e1_ > 0.f ? e1_ : 0.2f * e1_; \
    e2_ = e2_ > 0.f ? e2_ : 0.2f * e2_; \
    float w0_ = __expf(e0_), w1_ = __expf(e1_), w2_ = __expf(e2_); \
    const float2* fr_ = (const float2*)(g_f + sb_ * 192); \
    float2 f0_ = __ldg(fr_ + lane); \
    float2 f1_ = __ldg(fr_ + 32 + lane); \
    float2 f2_ = __ldg(fr_ + 64 + lane); \
    z0 += w0_; z1 += w1_; z2 += w2_; \
    t0.x += w0_ * f0_.x; t0.y += w0_ * f0_.y; \
    t1.x += w1_ * f1_.x; t1.y += w1_ * f1_.y; \
    t2.x += w2_ * f2_.x; t2.y += w2_ * f2_.y; }
#pragma unroll
    for (int r = 0; r < 3; r++) {
        int idx = r * cN + n;
        float4 er = __ldg((const float4*)g_er4 + idx);
        float z0 = 0.f, z1 = 0.f, z2 = 0.f;
        float2 t0 = {0.f, 0.f}, t1 = {0.f, 0.f}, t2 = {0.f, 0.f};
        int beg = g_off[idx], end = g_off[idx + 1];
        int j = beg;
        for (; j + 4 <= end; j += 4) { GG_BODY(j) GG_BODY(j + 1) GG_BODY(j + 2) GG_BODY(j + 3) }
        for (; j < end; ++j) { GG_BODY(j) }
        float r0 = 1.f / (z0 + 1e-9f), r1 = 1.f / (z1 + 1e-9f), r2 = 1.f / (z2 + 1e-9f);
        acc0.x += t0.x * r0; acc0.y += t0.y * r0;
        acc1.x += t1.x * r1; acc1.y += t1.y * r1;
        acc2.x += t2.x * r2; acc2.y += t2.y * r2;
    }
#undef GG_BODY
    float2* o0 = (float2*)(g_gat + (size_t)n * 192)       + lane;
    float2* o1 = (float2*)(g_gat + (size_t)n * 192 + 64)  + lane;
    float2* o2 = (float2*)(g_gat + (size_t)n * 192 + 128) + lane;
    o0->x = fmaxf(acc0.x, 0.f); o0->y = fmaxf(acc0.y, 0.f);
    o1->x = fmaxf(acc1.x, 0.f); o1->y = fmaxf(acc1.y, 0.f);
    o2->x = fmaxf(acc2.x, 0.f); o2->y = fmaxf(acc2.y, 0.f);
}

// ------------------------- conv2 gather + sigmoid (fused) -------------------------
__global__ void __launch_bounds__(256) k_gath2(const float* __restrict__ b2) {
    int gw = blockIdx.x * 8 + (threadIdx.x >> 5);
    int lane = threadIdx.x & 31;
    if (gw >= cN) return;
    int n = gw;
    int p = lane * 2;
    float bx = b2[p]     + b2[64 + p]     + b2[128 + p];
    float by = b2[p + 1] + b2[64 + p + 1] + b2[128 + p + 1];
    float2 acc0 = {bx, by}, acc1 = {bx, by}, acc2 = {bx, by};
#define G2_BODY(J) { \
    int s_ = __ldg(&g_esrc[J]); \
    float sc_ = __ldg(&g_ns[r * cN + s_]) * nd; \
    const float2* base_ = (const float2*)(g_xW2 + ((size_t)r * cM + (size_t)s_ * 3) * 64); \
    float2 f0_ = __ldg(base_ + lane); \
    float2 f1_ = __ldg(base_ + 32 + lane); \
    float2 f2_ = __ldg(base_ + 64 + lane); \
    acc0.x += sc_ * f0_.x; acc0.y += sc_ * f0_.y; \
    acc1.x += sc_ * f1_.x; acc1.y += sc_ * f1_.y; \
    acc2.x += sc_ * f2_.x; acc2.y += sc_ * f2_.y; }
#pragma unroll
    for (int r = 0; r < 3; r++) {
        int idx = r * cN + n;
        float nd = g_nd[idx];
        int beg = g_off[idx], end = g_off[idx + 1];
        int j = beg;
        for (; j + 4 <= end; j += 4) { G2_BODY(j) G2_BODY(j + 1) G2_BODY(j + 2) G2_BODY(j + 3) }
        for (; j < end; ++j) { G2_BODY(j) }
    }
#undef G2_BODY
    float2* o0 = (float2*)(g_acc2 + (size_t)n * 192)       + lane;
    float2* o1 = (float2*)(g_acc2 + (size_t)n * 192 + 64)  + lane;
    float2* o2 = (float2*)(g_acc2 + (size_t)n * 192 + 128) + lane;
    o0->x = sigmoidf_(acc0.x); o0->y = sigmoidf_(acc0.y);
    o1->x = sigmoidf_(acc1.x); o1->y = sigmoidf_(acc1.y);
    o2->x = sigmoidf_(acc2.x); o2->y = sigmoidf_(acc2.y);
}

// ------------------------- node counts per graph -------------------------
__global__ void k_cnt(const int* __restrict__ gid) {
    int i = blockIdx.x * blockDim.x + threadIdx.x;
    if (i >= cN) return;
    int g = gid[i];
    unsigned m = __match_any_sync(__activemask(), g);
    int leader = __ffs(m) - 1;
    if ((threadIdx.x & 31) == leader)
        atomicAdd(&g_cnt[g], (float)__popc(m));
}

// ------------------------- graph pooling (acc2 already sigmoid'd) -------------------------
__global__ void k_pool(const int* __restrict__ gid) {
    int n0 = blockIdx.x * 64;
    int j  = threadIdx.x;                        // 192 threads
    int curg = -1;
    float a = 0.f;
#pragma unroll 1
    for (int m = 0; m < 64; m++) {
        int n = n0 + m;
        if (n >= cN) break;
        int g = __ldg(&gid[n]);
        float v = g_acc2[(size_t)n * 192 + j];
        if (g != curg) {
            if (curg >= 0) atomicAdd(&g_pool[curg * 192 + j], a);
            curg = g; a = 0.f;
        }
        a += v;
    }
    if (curg >= 0) atomicAdd(&g_pool[curg * 192 + j], a);
}

// ------------------------- final classifier + mean -------------------------
__global__ void k_final(const float* __restrict__ Wc, const float* __restrict__ bc,
                        float* __restrict__ out) {
    int t = threadIdx.x;                          // 384 threads
    int b = t / 48, rem = t % 48, h = rem / 16, c = rem & 15;
    float inv = 1.f / fmaxf(g_cnt[b], 1.f);
    const float* P = g_pool + (b * 3 + h) * 64;
    float dot = bc[c];
#pragma unroll
    for (int k = 0; k < 64; k++) dot += P[k] * inv * Wc[k * 16 + c];
    float sg = 1.f / (1.f + expf(-dot));
#pragma unroll
    for (int off = 8; off; off >>= 1) sg += __shfl_xor_sync(0xffffffffu, sg, off);
    if (c == 0) out[b * 3 + h] = sg * (1.f / 16.f);
}

// ------------------------- launcher -------------------------
extern "C" void kernel_launch(void* const* d_in, const int* in_sizes, int n_in,
                              void* d_out, int out_size) {
    const float* x   = (const float*)d_in[0];
    const int*   src = (const int*)  d_in[1];
    const int*   dst = (const int*)  d_in[2];
    const int*   gid = (const int*)  d_in[3];
    const float* W1  = (const float*)d_in[4];
    const float* b1  = (const float*)d_in[5];
    const float* Wg  = (const float*)d_in[6];
    const float* al  = (const float*)d_in[7];
    const float* ar  = (const float*)d_in[8];
    const float* bg  = (const float*)d_in[9];
    const float* W2  = (const float*)d_in[10];
    const float* b2  = (const float*)d_in[11];
    const float* Wc  = (const float*)d_in[12];
    const float* bc  = (const float*)d_in[13];
    float* out = (float*)d_out;

    // resolve device scratch addresses
    float *pxW, *ph1, *pf, *pgat, *pxW2;
    cudaGetSymbolAddress((void**)&pxW,  g_xW);
    cudaGetSymbolAddress((void**)&ph1,  g_h1);
    cudaGetSymbolAddress((void**)&pf,   g_f);
    cudaGetSymbolAddress((void**)&pgat, g_gat);
    cudaGetSymbolAddress((void**)&pxW2, g_xW2);

    constexpr int SM128 = (64 * (128 + 4) + 128 * 64) * 4;   // 66560 B
    constexpr int SM64  = (64 * (64 + 4)  + 64 * 64)  * 4;   // 33792 B
    cudaFuncSetAttribute(k_gemm<128>, cudaFuncAttributeMaxDynamicSharedMemorySize, SM128);
    cudaFuncSetAttribute(k_gemm<64>,  cudaFuncAttributeMaxDynamicSharedMemorySize, SM64);

    // CSR build
    k_init0<<<(cRN + 255) / 256, 256>>>();
    k_deg<<<(cRE + 255) / 256, 256>>>(src, dst);
    k_norm<<<(cRN + 255) / 256, 256>>>();
    k_scanA<<<SCAN_NB, 256>>>();
    k_scanB<<<1, 256>>>();
    k_scanC<<<(cRN + 255) / 256, 256>>>();
    k_fill<<<(cRE + 255) / 256, 256>>>(src, dst);

    // layer 1: xW[r] = x @ W1[r]
    k_gemm<128><<<dim3((cN + 63) / 64, 3, 1), 256, SM128>>>(
        x, 128, W1, 64, (size_t)128 * 64, pxW, 64, (size_t)cN * 64, cN);
    k_gath1<<<(cN + 7) / 8, 256>>>(b1);

    // GAT: f[r] = h1 @ Wg[r]  (3 col tiles of 64)
    k_gemm<64><<<dim3((cN + 63) / 64, 3, 3), 256, SM64>>>(
        ph1, 64, Wg, 192, (size_t)64 * 192, pf, 192, (size_t)cN * 192, cN);
    dim3 gE((cN + 31) / 32, cR);
    k_eler<<<gE, 192>>>(al, ar);
    k_ggat<<<(cN + 7) / 8, 256>>>(bg);

    // layer 2: xW2[r] = gat @ W2[r]   (rows = cM = N*H)
    k_gemm<64><<<dim3((cM + 63) / 64, 3, 1), 256, SM64>>>(
        pgat, 64, W2, 64, (size_t)64 * 64, pxW2, 64, (size_t)cM * 64, cM);
    k_gath2<<<(cN + 7) / 8, 256>>>(b2);

    // pooling + classifier
    k_cnt<<<(cN + 255) / 256, 256>>>(gid);
    k_pool<<<(cN + 63) / 64, 192>>>(gid);
    k_final<<<1, 384>>>(Wc, bc, out);
}

// round 7
// speedup vs baseline: 2.5326x; 1.0885x over previous
#include <cuda_runtime.h>

// Problem constants (fixed by the reference)
constexpr int cN   = 50000;
constexpr int cE   = 400000;
constexpr int cR   = 3;
constexpr int cH   = 3;
constexpr int cIN  = 128;
constexpr int cHID = 64;
constexpr int cOUT = 64;
constexpr int cC   = 16;
constexpr int cB   = 8;
constexpr int cF2  = cH * cHID;   // 192
constexpr int cM   = cN * cH;     // 150000 rows for conv2
constexpr int cRN  = cR * cN;     // 150000
constexpr int cRE  = cR * cE;     // 1.2M
constexpr int SCAN_NB = (cRN + 1023) / 1024;  // 147

// ------------------------- device scratch (static, no alloc) -------------------------
__device__ int      g_outdeg[cRN];
__device__ int      g_indeg[cRN];
__device__ float    g_ns[cRN];
__device__ float    g_nd[cRN];
__device__ int      g_off[cRN + 1];
__device__ int      g_cursor[cRN];
__device__ int      g_bsum[256];
__device__ int      g_esrc[cRE];
__device__ float    g_xW[cRN * cHID];
__device__ float    g_h1[cN * cHID];
__device__ float    g_f[(size_t)cRN * cF2];
__device__ float    g_el4[cRN * 4];                 // padded: [idx*4 + h], h<3
__device__ float    g_er4[cRN * 4];
__device__ float    g_gat[cN * cF2];
__device__ float    g_xW2[(size_t)cR * cM * cOUT];
__device__ float    g_acc2[cM * cOUT];
__device__ float    g_pool[cB * cF2];
__device__ float    g_cnt[cB];

__device__ __forceinline__ float sigmoidf_(float v) { return 1.f / (1.f + __expf(-v)); }

// ------------------------- init -------------------------
__global__ void k_init0() {
    int i = blockIdx.x * blockDim.x + threadIdx.x;
    if (i < cRN) { g_outdeg[i] = 0; g_indeg[i] = 0; }
    if (i < cB * cF2) g_pool[i] = 0.f;
    if (i < cB)       g_cnt[i] = 0.f;
}

// ------------------------- degrees -------------------------
__global__ void k_deg(const int* __restrict__ src, const int* __restrict__ dst) {
    int i = blockIdx.x * blockDim.x + threadIdx.x;
    if (i >= cRE) return;
    int r = i / cE;
    atomicAdd(&g_outdeg[r * cN + src[i]], 1);
    atomicAdd(&g_indeg[r * cN + dst[i]], 1);
}
__global__ void k_norm() {
    int i = blockIdx.x * blockDim.x + threadIdx.x;
    if (i >= cRN) return;
    g_ns[i] = rsqrtf(fmaxf((float)g_outdeg[i], 1.f));
    g_nd[i] = rsqrtf(fmaxf((float)g_indeg[i], 1.f));
}

// ------------------------- exclusive scan of indeg -> offsets -------------------------
__global__ void k_scanA() {
    __shared__ int wsum[8];
    int tid = threadIdx.x, lane = tid & 31, wid = tid >> 5;
    int idx0 = blockIdx.x * 1024 + tid * 4;
    int v[4]; int s = 0;
#pragma unroll
    for (int k = 0; k < 4; k++) {
        int i = idx0 + k;
        int x = (i < cRN) ? g_indeg[i] : 0;
        v[k] = s; s += x;
    }
    int incl = s;
#pragma unroll
    for (int o = 1; o < 32; o <<= 1) {
        int t = __shfl_up_sync(0xffffffffu, incl, o);
        if (lane >= o) incl += t;
    }
    int excl = incl - s;
    if (lane == 31) wsum[wid] = incl;
    __syncthreads();
    if (tid == 0) {
        int a = 0;
#pragma unroll
        for (int w = 0; w < 8; w++) { int t = wsum[w]; wsum[w] = a; a += t; }
        g_bsum[blockIdx.x] = a;
    }
    __syncthreads();
    int base = wsum[wid] + excl;
#pragma unroll
    for (int k = 0; k < 4; k++) {
        int i = idx0 + k;
        if (i < cRN) g_off[i] = base + v[k];
    }
}
__global__ void k_scanB() {
    __shared__ int wsum[8];
    int tid = threadIdx.x, lane = tid & 31, wid = tid >> 5;
    int v = (tid < SCAN_NB) ? g_bsum[tid] : 0;
    int incl = v;
#pragma unroll
    for (int o = 1; o < 32; o <<= 1) {
        int t = __shfl_up_sync(0xffffffffu, incl, o);
        if (lane >= o) incl += t;
    }
    if (lane == 31) wsum[wid] = incl;
    __syncthreads();
    if (tid == 0) {
        int a = 0;
#pragma unroll
        for (int w = 0; w < 8; w++) { int t = wsum[w]; wsum[w] = a; a += t; }
    }
    __syncthreads();
    if (tid < SCAN_NB) g_bsum[tid] = wsum[wid] + incl - v;
}
__global__ void k_scanC() {
    int i = blockIdx.x * blockDim.x + threadIdx.x;
    if (i >= cRN) return;
    int o = g_off[i] + g_bsum[i >> 10];
    g_off[i] = o;
    g_cursor[i] = o;
    if (i == 0) g_off[cRN] = cRE;
}
__global__ void k_fill(const int* __restrict__ src, const int* __restrict__ dst) {
    int i = blockIdx.x * blockDim.x + threadIdx.x;
    if (i >= cRE) return;
    int r = i / cE;
    int pos = atomicAdd(&g_cursor[r * cN + dst[i]], 1);
    g_esrc[pos] = src[i];
}

// ------------------------- GEMM: C[rows, 64·gz] = A[rows,K] @ B[r][K,·] -------------------------
template<int K>
__global__ void __launch_bounds__(256) k_gemm(
    const float* __restrict__ A, int ldA,
    const float* __restrict__ B, int ldB, size_t sBrel,
    float* __restrict__ C, int ldC, size_t sCrel,
    int rows)
{
    extern __shared__ float sm[];
    constexpr int SAS = K + 4;
    float* sA = sm;                      // [64][SAS]
    float* sB = sm + 64 * SAS;           // [K][64]
    int r = blockIdx.y, ct = blockIdx.z;
    int n0 = blockIdx.x * 64;
    int tid = threadIdx.x;
    const float* Ab = A + (size_t)n0 * ldA;
    const float* Bb = B + r * sBrel + ct * 64;
    for (int i = tid; i < 64 * (K / 4); i += 256) {
        int row = i / (K / 4), c4 = i % (K / 4);
        float4 v = (n0 + row < rows)
            ? __ldg((const float4*)(Ab + (size_t)row * ldA) + c4)
            : make_float4(0.f, 0.f, 0.f, 0.f);
        *(float4*)(sA + row * SAS + c4 * 4) = v;
    }
    for (int i = tid; i < K * 16; i += 256) {
        int k = i / 16, c4 = i % 16;
        float4 v = __ldg((const float4*)(Bb + (size_t)k * ldB) + c4);
        *(float4*)(sB + k * 64 + c4 * 4) = v;
    }
    __syncthreads();

    int ty = tid >> 4, tx = tid & 15;
    int row0 = ty * 4, col0 = tx * 4;
    float acc[4][4];
#pragma unroll
    for (int i = 0; i < 4; i++)
#pragma unroll
        for (int j = 0; j < 4; j++) acc[i][j] = 0.f;

    const float* a0 = sA + (row0 + 0) * SAS;
    const float* a1 = sA + (row0 + 1) * SAS;
    const float* a2 = sA + (row0 + 2) * SAS;
    const float* a3 = sA + (row0 + 3) * SAS;
#pragma unroll 2
    for (int k = 0; k < K; k++) {
        float4 b = *(const float4*)(sB + k * 64 + col0);
        float v0 = a0[k], v1 = a1[k], v2 = a2[k], v3 = a3[k];
        acc[0][0] += v0 * b.x; acc[0][1] += v0 * b.y; acc[0][2] += v0 * b.z; acc[0][3] += v0 * b.w;
        acc[1][0] += v1 * b.x; acc[1][1] += v1 * b.y; acc[1][2] += v1 * b.z; acc[1][3] += v1 * b.w;
        acc[2][0] += v2 * b.x; acc[2][1] += v2 * b.y; acc[2][2] += v2 * b.z; acc[2][3] += v2 * b.w;
        acc[3][0] += v3 * b.x; acc[3][1] += v3 * b.y; acc[3][2] += v3 * b.z; acc[3][3] += v3 * b.w;
    }
#pragma unroll
    for (int i = 0; i < 4; i++) {
        int n = n0 + row0 + i;
        if (n < rows) {
            float* Cp = C + r * sCrel + (size_t)n * ldC + ct * 64 + col0;
            *(float4*)Cp = make_float4(acc[i][0], acc[i][1], acc[i][2], acc[i][3]);
        }
    }
}

// ------------------------- mmF GEMM with fused el/er epilogue -------------------------
__global__ void __launch_bounds__(256) k_gemmF(
    const float* __restrict__ A,            // h1 [cN,64]
    const float* __restrict__ Wg,           // [R,64,192]
    const float* __restrict__ al,           // [R,3,64]
    const float* __restrict__ ar,
    float* __restrict__ C)                  // g_f [R,cN,192]
{
    extern __shared__ float sm[];
    constexpr int K = 64, SAS = K + 4;
    float* sA = sm;
    float* sB = sm + 64 * SAS;
    int r = blockIdx.y, ct = blockIdx.z;
    int n0 = blockIdx.x * 64;
    int tid = threadIdx.x;
    const float* Ab = A + (size_t)n0 * 64;
    const float* Bb = Wg + r * (64 * 192) + ct * 64;
    for (int i = tid; i < 64 * 16; i += 256) {
        int row = i / 16, c4 = i % 16;
        float4 v = (n0 + row < cN)
            ? __ldg((const float4*)(Ab + (size_t)row * 64) + c4)
            : make_float4(0.f, 0.f, 0.f, 0.f);
        *(float4*)(sA + row * SAS + c4 * 4) = v;
    }
    for (int i = tid; i < K * 16; i += 256) {
        int k = i / 16, c4 = i % 16;
        float4 v = __ldg((const float4*)(Bb + (size_t)k * 192) + c4);
        *(float4*)(sB + k * 64 + c4 * 4) = v;
    }
    __syncthreads();

    int ty = tid >> 4, tx = tid & 15;
    int row0 = ty * 4, col0 = tx * 4;
    float acc[4][4];
#pragma unroll
    for (int i = 0; i < 4; i++)
#pragma unroll
        for (int j = 0; j < 4; j++) acc[i][j] = 0.f;

    const float* a0 = sA + (row0 + 0) * SAS;
    const float* a1 = sA + (row0 + 1) * SAS;
    const float* a2 = sA + (row0 + 2) * SAS;
    const float* a3 = sA + (row0 + 3) * SAS;
#pragma unroll 2
    for (int k = 0; k < K; k++) {
        float4 b = *(const float4*)(sB + k * 64 + col0);
        float v0 = a0[k], v1 = a1[k], v2 = a2[k], v3 = a3[k];
        acc[0][0] += v0 * b.x; acc[0][1] += v0 * b.y; acc[0][2] += v0 * b.z; acc[0][3] += v0 * b.w;
        acc[1][0] += v1 * b.x; acc[1][1] += v1 * b.y; acc[1][2] += v1 * b.z; acc[1][3] += v1 * b.w;
        acc[2][0] += v2 * b.x; acc[2][1] += v2 * b.y; acc[2][2] += v2 * b.z; acc[2][3] += v2 * b.w;
        acc[3][0] += v3 * b.x; acc[3][1] += v3 * b.y; acc[3][2] += v3 * b.z; acc[3][3] += v3 * b.w;
    }
#pragma unroll
    for (int i = 0; i < 4; i++) {
        int n = n0 + row0 + i;
        if (n < cN) {
            float* Cp = C + (size_t)r * cN * 192 + (size_t)n * 192 + ct * 64 + col0;
            *(float4*)Cp = make_float4(acc[i][0], acc[i][1], acc[i][2], acc[i][3]);
        }
    }
    // fused el/er: reduce partial head-dots across the 16 tx threads of each row
    float4 av = __ldg((const float4*)(al + r * 192 + ct * 64 + col0));
    float4 rv = __ldg((const float4*)(ar + r * 192 + ct * 64 + col0));
#pragma unroll
    for (int i = 0; i < 4; i++) {
        float pl = acc[i][0] * av.x + acc[i][1] * av.y + acc[i][2] * av.z + acc[i][3] * av.w;
        float pr = acc[i][0] * rv.x + acc[i][1] * rv.y + acc[i][2] * rv.z + acc[i][3] * rv.w;
#pragma unroll
        for (int o = 8; o; o >>= 1) {
            pl += __shfl_xor_sync(0xffffffffu, pl, o);
            pr += __shfl_xor_sync(0xffffffffu, pr, o);
        }
        int n = n0 + row0 + i;
        if (tx == 0 && n < cN) {
            g_el4[(r * cN + n) * 4 + ct] = pl;
            g_er4[(r * cN + n) * 4 + ct] = pr;
        }
    }
}

// ------------------------- conv1 gather + L2 normalize (fused) -------------------------
__global__ void __launch_bounds__(256) k_gath1(const float* __restrict__ b1) {
    int gw = blockIdx.x * 8 + (threadIdx.x >> 5);
    int lane = threadIdx.x & 31;
    if (gw >= cN) return;
    int n = gw;
    int p = lane * 2;
    float2 a;
    a.x = b1[p]     + b1[64 + p]     + b1[128 + p];
    a.y = b1[p + 1] + b1[64 + p + 1] + b1[128 + p + 1];
#define G1_BODY(J) { \
    int s_ = __ldg(&g_esrc[J]); \
    float sc_ = __ldg(&g_ns[r * cN + s_]) * nd; \
    float2 v_ = __ldg((const float2*)(g_xW + (size_t)(r * cN + s_) * 64) + lane); \
    a.x += sc_ * v_.x; a.y += sc_ * v_.y; }
#pragma unroll
    for (int r = 0; r < 3; r++) {
        int idx = r * cN + n;
        float nd = g_nd[idx];
        int beg = g_off[idx], end = g_off[idx + 1];
        int j = beg;
        for (; j + 4 <= end; j += 4) { G1_BODY(j) G1_BODY(j + 1) G1_BODY(j + 2) G1_BODY(j + 3) }
        for (; j < end; ++j) { G1_BODY(j) }
    }
#undef G1_BODY
    float ss = a.x * a.x + a.y * a.y;
#pragma unroll
    for (int o = 16; o; o >>= 1) ss += __shfl_xor_sync(0xffffffffu, ss, o);
    float inv = 1.f / fmaxf(sqrtf(ss), 1e-12f);
    float2* outp = (float2*)(g_h1 + (size_t)n * 64) + lane;
    outp->x = a.x * inv; outp->y = a.y * inv;
}

// ------------------------- GAT gather: shift-free softmax + weighted agg + relu -------------------------
__global__ void __launch_bounds__(256) k_ggat(const float* __restrict__ bg) {
    int gw = blockIdx.x * 8 + (threadIdx.x >> 5);
    int lane = threadIdx.x & 31;
    if (gw >= cN) return;
    int n = gw;
    int p = lane * 2;
    float2 acc0, acc1, acc2;
    acc0.x = bg[p]          + bg[192 + p]          + bg[384 + p];
    acc0.y = bg[p + 1]      + bg[192 + p + 1]      + bg[384 + p + 1];
    acc1.x = bg[64 + p]     + bg[256 + p]          + bg[448 + p];
    acc1.y = bg[64 + p + 1] + bg[256 + p + 1]      + bg[448 + p + 1];
    acc2.x = bg[128 + p]    + bg[320 + p]          + bg[512 + p];
    acc2.y = bg[128 + p + 1]+ bg[320 + p + 1]      + bg[512 + p + 1];
#define GG_BODY(J) { \
    int s_ = __ldg(&g_esrc[J]); \
    size_t sb_ = (size_t)(r * cN + s_); \
    float4 el_ = __ldg((const float4*)g_el4 + sb_); \
    float e0_ = el_.x + er.x, e1_ = el_.y + er.y, e2_ = el_.z + er.z; \
    e0_ = e0_ > 0.f ? e0_ : 0.2f * e0_; \
    e1_ = e1_ > 0.f ? e1_ : 0.2f * e1_; \
    e2_ = e2_ > 0.f ? e2_ : 0.2f * e2_; \
    float w0_ = __expf(e0_), w1_ = __expf(e1_), w2_ = __expf(e2_); \
    const float2* fr_ = (const float2*)(g_f + sb_ * 192); \
    float2 f0_ = __ldg(fr_ + lane); \
    float2 f1_ = __ldg(fr_ + 32 + lane); \
    float2 f2_ = __ldg(fr_ + 64 + lane); \
    z0 += w0_; z1 += w1_; z2 += w2_; \
    t0.x += w0_ * f0_.x; t0.y += w0_ * f0_.y; \
    t1.x += w1_ * f1_.x; t1.y += w1_ * f1_.y; \
    t2.x += w2_ * f2_.x; t2.y += w2_ * f2_.y; }
#pragma unroll
    for (int r = 0; r < 3; r++) {
        int idx = r * cN + n;
        float4 er = __ldg((const float4*)g_er4 + idx);
        float z0 = 0.f, z1 = 0.f, z2 = 0.f;
        float2 t0 = {0.f, 0.f}, t1 = {0.f, 0.f}, t2 = {0.f, 0.f};
        int beg = g_off[idx], end = g_off[idx + 1];
        int j = beg;
        for (; j + 4 <= end; j += 4) { GG_BODY(j) GG_BODY(j + 1) GG_BODY(j + 2) GG_BODY(j + 3) }
        for (; j < end; ++j) { GG_BODY(j) }
        float r0 = 1.f / (z0 + 1e-9f), r1 = 1.f / (z1 + 1e-9f), r2 = 1.f / (z2 + 1e-9f);
        acc0.x += t0.x * r0; acc0.y += t0.y * r0;
        acc1.x += t1.x * r1; acc1.y += t1.y * r1;
        acc2.x += t2.x * r2; acc2.y += t2.y * r2;
    }
#undef GG_BODY
    float2* o0 = (float2*)(g_gat + (size_t)n * 192)       + lane;
    float2* o1 = (float2*)(g_gat + (size_t)n * 192 + 64)  + lane;
    float2* o2 = (float2*)(g_gat + (size_t)n * 192 + 128) + lane;
    o0->x = fmaxf(acc0.x, 0.f); o0->y = fmaxf(acc0.y, 0.f);
    o1->x = fmaxf(acc1.x, 0.f); o1->y = fmaxf(acc1.y, 0.f);
    o2->x = fmaxf(acc2.x, 0.f); o2->y = fmaxf(acc2.y, 0.f);
}

// ------------------------- conv2 gather + sigmoid (fused) -------------------------
__global__ void __launch_bounds__(256) k_gath2(const float* __restrict__ b2) {
    int gw = blockIdx.x * 8 + (threadIdx.x >> 5);
    int lane = threadIdx.x & 31;
    if (gw >= cN) return;
    int n = gw;
    int p = lane * 2;
    float bx = b2[p]     + b2[64 + p]     + b2[128 + p];
    float by = b2[p + 1] + b2[64 + p + 1] + b2[128 + p + 1];
    float2 acc0 = {bx, by}, acc1 = {bx, by}, acc2 = {bx, by};
#define G2_BODY(J) { \
    int s_ = __ldg(&g_esrc[J]); \
    float sc_ = __ldg(&g_ns[r * cN + s_]) * nd; \
    const float2* base_ = (const float2*)(g_xW2 + ((size_t)r * cM + (size_t)s_ * 3) * 64); \
    float2 f0_ = __ldg(base_ + lane); \
    float2 f1_ = __ldg(base_ + 32 + lane); \
    float2 f2_ = __ldg(base_ + 64 + lane); \
    acc0.x += sc_ * f0_.x; acc0.y += sc_ * f0_.y; \
    acc1.x += sc_ * f1_.x; acc1.y += sc_ * f1_.y; \
    acc2.x += sc_ * f2_.x; acc2.y += sc_ * f2_.y; }
#pragma unroll
    for (int r = 0; r < 3; r++) {
        int idx = r * cN + n;
        float nd = g_nd[idx];
        int beg = g_off[idx], end = g_off[idx + 1];
        int j = beg;
        for (; j + 4 <= end; j += 4) { G2_BODY(j) G2_BODY(j + 1) G2_BODY(j + 2) G2_BODY(j + 3) }
        for (; j < end; ++j) { G2_BODY(j) }
    }
#undef G2_BODY
    float2* o0 = (float2*)(g_acc2 + (size_t)n * 192)       + lane;
    float2* o1 = (float2*)(g_acc2 + (size_t)n * 192 + 64)  + lane;
    float2* o2 = (float2*)(g_acc2 + (size_t)n * 192 + 128) + lane;
    o0->x = sigmoidf_(acc0.x); o0->y = sigmoidf_(acc0.y);
    o1->x = sigmoidf_(acc1.x); o1->y = sigmoidf_(acc1.y);
    o2->x = sigmoidf_(acc2.x); o2->y = sigmoidf_(acc2.y);
}

// ------------------------- node counts per graph -------------------------
__global__ void k_cnt(const int* __restrict__ gid) {
    int i = blockIdx.x * blockDim.x + threadIdx.x;
    if (i >= cN) return;
    int g = gid[i];
    unsigned m = __match_any_sync(__activemask(), g);
    int leader = __ffs(m) - 1;
    if ((threadIdx.x & 31) == leader)
        atomicAdd(&g_cnt[g], (float)__popc(m));
}

// ------------------------- graph pooling (acc2 already sigmoid'd) -------------------------
__global__ void k_pool(const int* __restrict__ gid) {
    int n0 = blockIdx.x * 64;
    int j  = threadIdx.x;                        // 192 threads
    int curg = -1;
    float a = 0.f;
#pragma unroll 1
    for (int m = 0; m < 64; m++) {
        int n = n0 + m;
        if (n >= cN) break;
        int g = __ldg(&gid[n]);
        float v = g_acc2[(size_t)n * 192 + j];
        if (g != curg) {
            if (curg >= 0) atomicAdd(&g_pool[curg * 192 + j], a);
            curg = g; a = 0.f;
        }
        a += v;
    }
    if (curg >= 0) atomicAdd(&g_pool[curg * 192 + j], a);
}

// ------------------------- final classifier + mean -------------------------
__global__ void k_final(const float* __restrict__ Wc, const float* __restrict__ bc,
                        float* __restrict__ out) {
    int t = threadIdx.x;                          // 384 threads
    int b = t / 48, rem = t % 48, h = rem / 16, c = rem & 15;
    float inv = 1.f / fmaxf(g_cnt[b], 1.f);
    const float* P = g_pool + (b * 3 + h) * 64;
    float dot = bc[c];
#pragma unroll
    for (int k = 0; k < 64; k++) dot += P[k] * inv * Wc[k * 16 + c];
    float sg = 1.f / (1.f + expf(-dot));
#pragma unroll
    for (int off = 8; off; off >>= 1) sg += __shfl_xor_sync(0xffffffffu, sg, off);
    if (c == 0) out[b * 3 + h] = sg * (1.f / 16.f);
}

// ------------------------- launcher -------------------------
extern "C" void kernel_launch(void* const* d_in, const int* in_sizes, int n_in,
                              void* d_out, int out_size) {
    const float* x   = (const float*)d_in[0];
    const int*   src = (const int*)  d_in[1];
    const int*   dst = (const int*)  d_in[2];
    const int*   gid = (const int*)  d_in[3];
    const float* W1  = (const float*)d_in[4];
    const float* b1  = (const float*)d_in[5];
    const float* Wg  = (const float*)d_in[6];
    const float* al  = (const float*)d_in[7];
    const float* ar  = (const float*)d_in[8];
    const float* bg  = (const float*)d_in[9];
    const float* W2  = (const float*)d_in[10];
    const float* b2  = (const float*)d_in[11];
    const float* Wc  = (const float*)d_in[12];
    const float* bc  = (const float*)d_in[13];
    float* out = (float*)d_out;

    float *pxW, *ph1, *pf, *pgat, *pxW2;
    cudaGetSymbolAddress((void**)&pxW,  g_xW);
    cudaGetSymbolAddress((void**)&ph1,  g_h1);
    cudaGetSymbolAddress((void**)&pf,   g_f);
    cudaGetSymbolAddress((void**)&pgat, g_gat);
    cudaGetSymbolAddress((void**)&pxW2, g_xW2);

    constexpr int SM128 = (64 * (128 + 4) + 128 * 64) * 4;   // 66560 B
    constexpr int SM64  = (64 * (64 + 4)  + 64 * 64)  * 4;   // 33792 B
    cudaFuncSetAttribute(k_gemm<128>, cudaFuncAttributeMaxDynamicSharedMemorySize, SM128);
    cudaFuncSetAttribute(k_gemm<64>,  cudaFuncAttributeMaxDynamicSharedMemorySize, SM64);
    cudaFuncSetAttribute(k_gemmF,     cudaFuncAttributeMaxDynamicSharedMemorySize, SM64);

    // side stream + events for fork-join inside graph capture (created once;
    // handles carry no state — the captured work is identical every call)
    static cudaStream_t s2 = nullptr;
    static cudaEvent_t ev_fork = nullptr, ev_join = nullptr;
    if (!s2) {
        cudaStreamCreateWithFlags(&s2, cudaStreamNonBlocking);
        cudaEventCreateWithFlags(&ev_fork, cudaEventDisableTiming);
        cudaEventCreateWithFlags(&ev_join, cudaEventDisableTiming);
    }

    // fork: mm1 (x @ W1, independent of CSR build) on side stream
    cudaEventRecord(ev_fork, 0);
    cudaStreamWaitEvent(s2, ev_fork, 0);
    k_gemm<128><<<dim3((cN + 63) / 64, 3, 1), 256, SM128, s2>>>(
        x, 128, W1, 64, (size_t)128 * 64, pxW, 64, (size_t)cN * 64, cN);
    cudaEventRecord(ev_join, s2);

    // main: CSR build
    k_init0<<<(cRN + 255) / 256, 256>>>();
    k_deg<<<(cRE + 255) / 256, 256>>>(src, dst);
    k_norm<<<(cRN + 255) / 256, 256>>>();
    k_scanA<<<SCAN_NB, 256>>>();
    k_scanB<<<1, 256>>>();
    k_scanC<<<(cRN + 255) / 256, 256>>>();
    k_fill<<<(cRE + 255) / 256, 256>>>(src, dst);
    k_cnt<<<(cN + 255) / 256, 256>>>(gid);

    // join: gath1 needs g_xW (s2) + CSR (main)
    cudaStreamWaitEvent(0, ev_join, 0);
    k_gath1<<<(cN + 7) / 8, 256>>>(b1);

    // GAT: f = h1 @ Wg with fused el/er epilogue
    k_gemmF<<<dim3((cN + 63) / 64, 3, 3), 256, SM64>>>(ph1, Wg, al, ar, pf);
    k_ggat<<<(cN + 7) / 8, 256>>>(bg);

    // layer 2
    k_gemm<64><<<dim3((cM + 63) / 64, 3, 1), 256, SM64>>>(
        pgat, 64, W2, 64, (size_t)64 * 64, pxW2, 64, (size_t)cM * 64, cM);
    k_gath2<<<(cN + 7) / 8, 256>>>(b2);

    // pooling + classifier
    k_pool<<<(cN + 63) / 64, 192>>>(gid);
    k_final<<<1, 384>>>(Wc, bc, out);
}

// round 9
// speedup vs baseline: 2.8481x; 1.1246x over previous
#include <cuda_runtime.h>
#include <cstdint>

// Problem constants (fixed by the reference)
constexpr int cN   = 50000;
constexpr int cE   = 400000;
constexpr int cR   = 3;
constexpr int cH   = 3;
constexpr int cIN  = 128;
constexpr int cHID = 64;
constexpr int cOUT = 64;
constexpr int cC   = 16;
constexpr int cB   = 8;
constexpr int cF2  = cH * cHID;   // 192
constexpr int cM   = cN * cH;     // 150000 rows for conv2
constexpr int cRN  = cR * cN;     // 150000
constexpr int cRE  = cR * cE;     // 1.2M
constexpr int SCAN_NB = (cRN + 1023) / 1024;  // 147

// ------------------------- device scratch (static, no alloc) -------------------------
__device__ int      g_outdeg[cRN];
__device__ int      g_indeg[cRN];
__device__ float    g_ns[cRN];
__device__ float    g_nd[cRN];
__device__ int      g_off[cRN + 1];
__device__ int      g_cursor[cRN];
__device__ int      g_bsum[256];
__device__ int      g_esrc[cRE];
__device__ float    g_xW[cRN * cHID];
__device__ float    g_h1[cN * cHID];
__device__ float    g_f[(size_t)cRN * cF2];
__device__ float    g_el4[cRN * 4];                 // padded: [idx*4 + h], h<3
__device__ float    g_er4[cRN * 4];
__device__ float    g_gat[cN * cF2];
__device__ float    g_xW2[(size_t)cR * cM * cOUT];
__device__ float    g_acc2[cM * cOUT];
__device__ float    g_pool[cB * cF2];
__device__ float    g_cnt[cB];

__device__ __forceinline__ float sigmoidf_(float v) { return 1.f / (1.f + __expf(-v)); }

// tf32 round (rna) — keeps fp32 register format, low 13 mantissa bits rounded away
__device__ __forceinline__ float tf32c(float x) {
    uint32_t o; asm("cvt.rna.tf32.f32 %0, %1;" : "=r"(o) : "f"(x));
    return __uint_as_float(o);
}
// m16n8k8 tf32 mma, fp32 accumulate (arch-agnostic PTX; HMMA on Blackwell)
__device__ __forceinline__ void mma8(float* c, uint32_t a0, uint32_t a1, uint32_t a2,
                                     uint32_t a3, uint32_t b0, uint32_t b1) {
    asm volatile("mma.sync.aligned.m16n8k8.row.col.f32.tf32.tf32.f32 "
                 "{%0,%1,%2,%3}, {%4,%5,%6,%7}, {%8,%9}, {%0,%1,%2,%3};"
                 : "+f"(c[0]), "+f"(c[1]), "+f"(c[2]), "+f"(c[3])
                 : "r"(a0), "r"(a1), "r"(a2), "r"(a3), "r"(b0), "r"(b1));
}

// ------------------------- init -------------------------
__global__ void k_init0() {
    int i = blockIdx.x * blockDim.x + threadIdx.x;
    if (i < cRN) { g_outdeg[i] = 0; g_indeg[i] = 0; }
    if (i < cB * cF2) g_pool[i] = 0.f;
    if (i < cB)       g_cnt[i] = 0.f;
}

// ------------------------- degrees -------------------------
__global__ void k_deg(const int* __restrict__ src, const int* __restrict__ dst) {
    int i = blockIdx.x * blockDim.x + threadIdx.x;
    if (i >= cRE) return;
    int r = i / cE;
    atomicAdd(&g_outdeg[r * cN + src[i]], 1);
    atomicAdd(&g_indeg[r * cN + dst[i]], 1);
}
__global__ void k_norm() {
    int i = blockIdx.x * blockDim.x + threadIdx.x;
    if (i >= cRN) return;
    g_ns[i] = rsqrtf(fmaxf((float)g_outdeg[i], 1.f));
    g_nd[i] = rsqrtf(fmaxf((float)g_indeg[i], 1.f));
}

// ------------------------- exclusive scan of indeg -> offsets -------------------------
__global__ void k_scanA() {
    __shared__ int wsum[8];
    int tid = threadIdx.x, lane = tid & 31, wid = tid >> 5;
    int idx0 = blockIdx.x * 1024 + tid * 4;
    int v[4]; int s = 0;
#pragma unroll
    for (int k = 0; k < 4; k++) {
        int i = idx0 + k;
        int x = (i < cRN) ? g_indeg[i] : 0;
        v[k] = s; s += x;
    }
    int incl = s;
#pragma unroll
    for (int o = 1; o < 32; o <<= 1) {
        int t = __shfl_up_sync(0xffffffffu, incl, o);
        if (lane >= o) incl += t;
    }
    int excl = incl - s;
    if (lane == 31) wsum[wid] = incl;
    __syncthreads();
    if (tid == 0) {
        int a = 0;
#pragma unroll
        for (int w = 0; w < 8; w++) { int t = wsum[w]; wsum[w] = a; a += t; }
        g_bsum[blockIdx.x] = a;
    }
    __syncthreads();
    int base = wsum[wid] + excl;
#pragma unroll
    for (int k = 0; k < 4; k++) {
        int i = idx0 + k;
        if (i < cRN) g_off[i] = base + v[k];
    }
}
__global__ void k_scanB() {
    __shared__ int wsum[8];
    int tid = threadIdx.x, lane = tid & 31, wid = tid >> 5;
    int v = (tid < SCAN_NB) ? g_bsum[tid] : 0;
    int incl = v;
#pragma unroll
    for (int o = 1; o < 32; o <<= 1) {
        int t = __shfl_up_sync(0xffffffffu, incl, o);
        if (lane >= o) incl += t;
    }
    if (lane == 31) wsum[wid] = incl;
    __syncthreads();
    if (tid == 0) {
        int a = 0;
#pragma unroll
        for (int w = 0; w < 8; w++) { int t = wsum[w]; wsum[w] = a; a += t; }
    }
    __syncthreads();
    if (tid < SCAN_NB) g_bsum[tid] = wsum[wid] + incl - v;
}
__global__ void k_scanC() {
    int i = blockIdx.x * blockDim.x + threadIdx.x;
    if (i >= cRN) return;
    int o = g_off[i] + g_bsum[i >> 10];
    g_off[i] = o;
    g_cursor[i] = o;
    if (i == 0) g_off[cRN] = cRE;
}
__global__ void k_fill(const int* __restrict__ src, const int* __restrict__ dst) {
    int i = blockIdx.x * blockDim.x + threadIdx.x;
    if (i >= cRE) return;
    int r = i / cE;
    int pos = atomicAdd(&g_cursor[r * cN + dst[i]], 1);
    g_esrc[pos] = src[i];
}

// ------------------------- FFMA GEMM (mm1 only, K=128; hidden behind CSR build) -------------------------
template<int K>
__global__ void __launch_bounds__(256) k_gemm(
    const float* __restrict__ A, int ldA,
    const float* __restrict__ B, int ldB, size_t sBrel,
    float* __restrict__ C, int ldC, size_t sCrel,
    int rows)
{
    extern __shared__ float sm[];
    constexpr int SAS = K + 4;
    float* sA = sm;
    float* sB = sm + 64 * SAS;
    int r = blockIdx.y, ct = blockIdx.z;
    int n0 = blockIdx.x * 64;
    int tid = threadIdx.x;
    const float* Ab = A + (size_t)n0 * ldA;
    const float* Bb = B + r * sBrel + ct * 64;
    for (int i = tid; i < 64 * (K / 4); i += 256) {
        int row = i / (K / 4), c4 = i % (K / 4);
        float4 v = (n0 + row < rows)
            ? __ldg((const float4*)(Ab + (size_t)row * ldA) + c4)
            : make_float4(0.f, 0.f, 0.f, 0.f);
        *(float4*)(sA + row * SAS + c4 * 4) = v;
    }
    for (int i = tid; i < K * 16; i += 256) {
        int k = i / 16, c4 = i % 16;
        float4 v = __ldg((const float4*)(Bb + (size_t)k * ldB) + c4);
        *(float4*)(sB + k * 64 + c4 * 4) = v;
    }
    __syncthreads();

    int ty = tid >> 4, tx = tid & 15;
    int row0 = ty * 4, col0 = tx * 4;
    float acc[4][4];
#pragma unroll
    for (int i = 0; i < 4; i++)
#pragma unroll
        for (int j = 0; j < 4; j++) acc[i][j] = 0.f;

    const float* a0 = sA + (row0 + 0) * SAS;
    const float* a1 = sA + (row0 + 1) * SAS;
    const float* a2 = sA + (row0 + 2) * SAS;
    const float* a3 = sA + (row0 + 3) * SAS;
#pragma unroll 2
    for (int k = 0; k < K; k++) {
        float4 b = *(const float4*)(sB + k * 64 + col0);
        float v0 = a0[k], v1 = a1[k], v2 = a2[k], v3 = a3[k];
        acc[0][0] += v0 * b.x; acc[0][1] += v0 * b.y; acc[0][2] += v0 * b.z; acc[0][3] += v0 * b.w;
        acc[1][0] += v1 * b.x; acc[1][1] += v1 * b.y; acc[1][2] += v1 * b.z; acc[1][3] += v1 * b.w;
        acc[2][0] += v2 * b.x; acc[2][1] += v2 * b.y; acc[2][2] += v2 * b.z; acc[2][3] += v2 * b.w;
        acc[3][0] += v3 * b.x; acc[3][1] += v3 * b.y; acc[3][2] += v3 * b.z; acc[3][3] += v3 * b.w;
    }
#pragma unroll
    for (int i = 0; i < 4; i++) {
        int n = n0 + row0 + i;
        if (n < rows) {
            float* Cp = C + r * sCrel + (size_t)n * ldC + ct * 64 + col0;
            *(float4*)Cp = make_float4(acc[i][0], acc[i][1], acc[i][2], acc[i][3]);
        }
    }
}

// ------------------------- tf32 mma.sync GEMM: C[64-tile, 64-cols@ct] = A[64,64] @ B[r][64, LDB] -------------------
// 128 threads / 4 warps; warp = 16 rows x 64 cols (8 col tiles, m16n8k8).
// ATT: fused el/er epilogue (col-tile ct == head index since heads are 64-col chunks).
template<int LDB, bool ATT>
__global__ void __launch_bounds__(128) k_hmm(
    const float* __restrict__ A,            // [rows, 64]
    const float* __restrict__ Bsrc,         // [R, 64, LDB]
    const float* __restrict__ al,           // [R, 3, 64] (ATT only)
    const float* __restrict__ ar,
    float* __restrict__ C,                  // [R, rows, LDB]
    int rows)
{
    __shared__ float sA[64][68];            // (4*gid+tig)%32 -> conflict-free A frags
    __shared__ float sB[64][72];            // (8*tig+gid)%32 -> conflict-free B frags
    __shared__ float sAl[2][64];
    int tid = threadIdx.x, warp = tid >> 5, lane = tid & 31;
    int gid = lane >> 2, tig = lane & 3;
    int r = blockIdx.y, ct = blockIdx.z;
    int n0 = blockIdx.x * 64;

    // load A tile [64,64], round to tf32
    const float* Ab = A + (size_t)n0 * 64;
    for (int i = tid; i < 64 * 16; i += 128) {
        int row = i >> 4, c4 = (i & 15) * 4;
        float4 v = (n0 + row < rows)
            ? __ldg((const float4*)(Ab + (size_t)row * 64 + c4))
            : make_float4(0.f, 0.f, 0.f, 0.f);
        sA[row][c4]     = tf32c(v.x);
        sA[row][c4 + 1] = tf32c(v.y);
        sA[row][c4 + 2] = tf32c(v.z);
        sA[row][c4 + 3] = tf32c(v.w);
    }
    // load B tile [64 k, 64 n] at col offset ct*64, round to tf32
    const float* Bb = Bsrc + (size_t)r * 64 * LDB + ct * 64;
    for (int i = tid; i < 64 * 16; i += 128) {
        int k = i >> 4, c4 = (i & 15) * 4;
        float4 v = __ldg((const float4*)(Bb + (size_t)k * LDB + c4));
        sB[k][c4]     = tf32c(v.x);
        sB[k][c4 + 1] = tf32c(v.y);
        sB[k][c4 + 2] = tf32c(v.z);
        sB[k][c4 + 3] = tf32c(v.w);
    }
    if (ATT && tid < 64) {
        sAl[0][tid] = __ldg(&al[r * 192 + ct * 64 + tid]);
        sAl[1][tid] = __ldg(&ar[r * 192 + ct * 64 + tid]);
    }
    __syncthreads();

    int r0 = warp * 16;
    float c[8][4];
#pragma unroll
    for (int t = 0; t < 8; t++)
#pragma unroll
        for (int j = 0; j < 4; j++) c[t][j] = 0.f;

#pragma unroll
    for (int kt = 0; kt < 8; kt++) {
        int k0 = kt * 8;
        uint32_t a0 = __float_as_uint(sA[r0 + gid][k0 + tig]);
        uint32_t a1 = __float_as_uint(sA[r0 + gid + 8][k0 + tig]);
        uint32_t a2 = __float_as_uint(sA[r0 + gid][k0 + tig + 4]);
        uint32_t a3 = __float_as_uint(sA[r0 + gid + 8][k0 + tig + 4]);
#pragma unroll
        for (int t = 0; t < 8; t++) {
            uint32_t b0 = __float_as_uint(sB[k0 + tig][t * 8 + gid]);
            uint32_t b1 = __float_as_uint(sB[k0 + tig + 4][t * 8 + gid]);
            mma8(c[t], a0, a1, a2, a3, b0, b1);
        }
    }

    int row0 = n0 + r0 + gid, row1 = row0 + 8;
    size_t base = (size_t)r * rows;
#pragma unroll
    for (int t = 0; t < 8; t++) {
        int col = ct * 64 + t * 8 + tig * 2;
        if (row0 < rows) *(float2*)(C + (base + row0) * LDB + col) = make_float2(c[t][0], c[t][1]);
        if (row1 < rows) *(float2*)(C + (base + row1) * LDB + col) = make_float2(c[t][2], c[t][3]);
    }

    if (ATT) {
        float pl0 = 0.f, pl1 = 0.f, pr0 = 0.f, pr1 = 0.f;
#pragma unroll
        for (int t = 0; t < 8; t++) {
            float l0 = sAl[0][t * 8 + tig * 2], l1 = sAl[0][t * 8 + tig * 2 + 1];
            float q0 = sAl[1][t * 8 + tig * 2], q1 = sAl[1][t * 8 + tig * 2 + 1];
            pl0 += c[t][0] * l0 + c[t][1] * l1;
            pl1 += c[t][2] * l0 + c[t][3] * l1;
            pr0 += c[t][0] * q0 + c[t][1] * q1;
            pr1 += c[t][2] * q0 + c[t][3] * q1;
        }
#pragma unroll
        for (int o = 1; o < 4; o <<= 1) {
            pl0 += __shfl_xor_sync(0xffffffffu, pl0, o);
            pl1 += __shfl_xor_sync(0xffffffffu, pl1, o);
            pr0 += __shfl_xor_sync(0xffffffffu, pr0, o);
            pr1 += __shfl_xor_sync(0xffffffffu, pr1, o);
        }
        if (tig == 0) {
            if (row0 < rows) { g_el4[(r * cN + row0) * 4 + ct] = pl0; g_er4[(r * cN + row0) * 4 + ct] = pr0; }
            if (row1 < rows) { g_el4[(r * cN + row1) * 4 + ct] = pl1; g_er4[(r * cN + row1) * 4 + ct] = pr1; }
        }
    }
}

// ------------------------- conv1 gather + L2 normalize (fused) -------------------------
__global__ void __launch_bounds__(256) k_gath1(const float* __restrict__ b1) {
    int gw = blockIdx.x * 8 + (threadIdx.x >> 5);
    int lane = threadIdx.x & 31;
    if (gw >= cN) return;
    int n = gw;
    int p = lane * 2;
    float2 a;
    a.x = b1[p]     + b1[64 + p]     + b1[128 + p];
    a.y = b1[p + 1] + b1[64 + p + 1] + b1[128 + p + 1];
#define G1_BODY(J) { \
    int s_ = __ldg(&g_esrc[J]); \
    float sc_ = __ldg(&g_ns[r * cN + s_]) * nd; \
    float2 v_ = __ldg((const float2*)(g_xW + (size_t)(r * cN + s_) * 64) + lane); \
    a.x += sc_ * v_.x; a.y += sc_ * v_.y; }
#pragma unroll
    for (int r = 0; r < 3; r++) {
        int idx = r * cN + n;
        float nd = g_nd[idx];
        int beg = g_off[idx], end = g_off[idx + 1];
        int j = beg;
        for (; j + 4 <= end; j += 4) { G1_BODY(j) G1_BODY(j + 1) G1_BODY(j + 2) G1_BODY(j + 3) }
        for (; j < end; ++j) { G1_BODY(j) }
    }
#undef G1_BODY
    float ss = a.x * a.x + a.y * a.y;
#pragma unroll
    for (int o = 16; o; o >>= 1) ss += __shfl_xor_sync(0xffffffffu, ss, o);
    float inv = 1.f / fmaxf(sqrtf(ss), 1e-12f);
    float2* outp = (float2*)(g_h1 + (size_t)n * 64) + lane;
    outp->x = a.x * inv; outp->y = a.y * inv;
}

// ------------------------- GAT gather: shift-free softmax + weighted agg + relu -------------------------
__global__ void __launch_bounds__(256) k_ggat(const float* __restrict__ bg) {
    int gw = blockIdx.x * 8 + (threadIdx.x >> 5);
    int lane = threadIdx.x & 31;
    if (gw >= cN) return;
    int n = gw;
    int p = lane * 2;
    float2 acc0, acc1, acc2;
    acc0.x = bg[p]          + bg[192 + p]          + bg[384 + p];
    acc0.y = bg[p + 1]      + bg[192 + p + 1]      + bg[384 + p + 1];
    acc1.x = bg[64 + p]     + bg[256 + p]          + bg[448 + p];
    acc1.y = bg[64 + p + 1] + bg[256 + p + 1]      + bg[448 + p + 1];
    acc2.x = bg[128 + p]    + bg[320 + p]          + bg[512 + p];
    acc2.y = bg[128 + p + 1]+ bg[320 + p + 1]      + bg[512 + p + 1];
#define GG_BODY(J) { \
    int s_ = __ldg(&g_esrc[J]); \
    size_t sb_ = (size_t)(r * cN + s_); \
    float4 el_ = __ldg((const float4*)g_el4 + sb_); \
    float e0_ = el_.x + er.x, e1_ = el_.y + er.y, e2_ = el_.z + er.z; \
    e0_ = e0_ > 0.f ? e0_ : 0.2f * e0_; \
    e1_ = e1_ > 0.f ? e1_ : 0.2f * e1_; \
    e2_ = e2_ > 0.f ? e2_ : 0.2f * e2_; \
    float w0_ = __expf(e0_), w1_ = __expf(e1_), w2_ = __expf(e2_); \
    const float2* fr_ = (const float2*)(g_f + sb_ * 192); \
    float2 f0_ = __ldg(fr_ + lane); \
    float2 f1_ = __ldg(fr_ + 32 + lane); \
    float2 f2_ = __ldg(fr_ + 64 + lane); \
    z0 += w0_; z1 += w1_; z2 += w2_; \
    t0.x += w0_ * f0_.x; t0.y += w0_ * f0_.y; \
    t1.x += w1_ * f1_.x; t1.y += w1_ * f1_.y; \
    t2.x += w2_ * f2_.x; t2.y += w2_ * f2_.y; }
#pragma unroll
    for (int r = 0; r < 3; r++) {
        int idx = r * cN + n;
        float4 er = __ldg((const float4*)g_er4 + idx);
        float z0 = 0.f, z1 = 0.f, z2 = 0.f;
        float2 t0 = {0.f, 0.f}, t1 = {0.f, 0.f}, t2 = {0.f, 0.f};
        int beg = g_off[idx], end = g_off[idx + 1];
        int j = beg;
        for (; j + 4 <= end; j += 4) { GG_BODY(j) GG_BODY(j + 1) GG_BODY(j + 2) GG_BODY(j + 3) }
        for (; j < end; ++j) { GG_BODY(j) }
        float r0 = 1.f / (z0 + 1e-9f), r1 = 1.f / (z1 + 1e-9f), r2 = 1.f / (z2 + 1e-9f);
        acc0.x += t0.x * r0; acc0.y += t0.y * r0;
        acc1.x += t1.x * r1; acc1.y += t1.y * r1;
        acc2.x += t2.x * r2; acc2.y += t2.y * r2;
    }
#undef GG_BODY
    float2* o0 = (float2*)(g_gat + (size_t)n * 192)       + lane;
    float2* o1 = (float2*)(g_gat + (size_t)n * 192 + 64)  + lane;
    float2* o2 = (float2*)(g_gat + (size_t)n * 192 + 128) + lane;
    o0->x = fmaxf(acc0.x, 0.f); o0->y = fmaxf(acc0.y, 0.f);
    o1->x = fmaxf(acc1.x, 0.f); o1->y = fmaxf(acc1.y, 0.f);
    o2->x = fmaxf(acc2.x, 0.f); o2->y = fmaxf(acc2.y, 0.f);
}

// ------------------------- conv2 gather + sigmoid (fused) -------------------------
__global__ void __launch_bounds__(256) k_gath2(const float* __restrict__ b2) {
    int gw = blockIdx.x * 8 + (threadIdx.x >> 5);
    int lane = threadIdx.x & 31;
    if (gw >= cN) return;
    int n = gw;
    int p = lane * 2;
    float bx = b2[p]     + b2[64 + p]     + b2[128 + p];
    float by = b2[p + 1] + b2[64 + p + 1] + b2[128 + p + 1];
    float2 acc0 = {bx, by}, acc1 = {bx, by}, acc2 = {bx, by};
#define G2_BODY(J) { \
    int s_ = __ldg(&g_esrc[J]); \
    float sc_ = __ldg(&g_ns[r * cN + s_]) * nd; \
    const float2* base_ = (const float2*)(g_xW2 + ((size_t)r * cM + (size_t)s_ * 3) * 64); \
    float2 f0_ = __ldg(base_ + lane); \
    float2 f1_ = __ldg(base_ + 32 + lane); \
    float2 f2_ = __ldg(base_ + 64 + lane); \
    acc0.x += sc_ * f0_.x; acc0.y += sc_ * f0_.y; \
    acc1.x += sc_ * f1_.x; acc1.y += sc_ * f1_.y; \
    acc2.x += sc_ * f2_.x; acc2.y += sc_ * f2_.y; }
#pragma unroll
    for (int r = 0; r < 3; r++) {
        int idx = r * cN + n;
        float nd = g_nd[idx];
        int beg = g_off[idx], end = g_off[idx + 1];
        int j = beg;
        for (; j + 4 <= end; j += 4) { G2_BODY(j) G2_BODY(j + 1) G2_BODY(j + 2) G2_BODY(j + 3) }
        for (; j < end; ++j) { G2_BODY(j) }
    }
#undef G2_BODY
    float2* o0 = (float2*)(g_acc2 + (size_t)n * 192)       + lane;
    float2* o1 = (float2*)(g_acc2 + (size_t)n * 192 + 64)  + lane;
    float2* o2 = (float2*)(g_acc2 + (size_t)n * 192 + 128) + lane;
    o0->x = sigmoidf_(acc0.x); o0->y = sigmoidf_(acc0.y);
    o1->x = sigmoidf_(acc1.x); o1->y = sigmoidf_(acc1.y);
    o2->x = sigmoidf_(acc2.x); o2->y = sigmoidf_(acc2.y);
}

// ------------------------- node counts per graph -------------------------
__global__ void k_cnt(const int* __restrict__ gid) {
    int i = blockIdx.x * blockDim.x + threadIdx.x;
    if (i >= cN) return;
    int g = gid[i];
    unsigned m = __match_any_sync(__activemask(), g);
    int leader = __ffs(m) - 1;
    if ((threadIdx.x & 31) == leader)
        atomicAdd(&g_cnt[g], (float)__popc(m));
}

// ------------------------- graph pooling (acc2 already sigmoid'd) -------------------------
__global__ void k_pool(const int* __restrict__ gid) {
    int n0 = blockIdx.x * 64;
    int j  = threadIdx.x;                        // 192 threads
    int curg = -1;
    float a = 0.f;
#pragma unroll 1
    for (int m = 0; m < 64; m++) {
        int n = n0 + m;
        if (n >= cN) break;
        int g = __ldg(&gid[n]);
        float v = g_acc2[(size_t)n * 192 + j];
        if (g != curg) {
            if (curg >= 0) atomicAdd(&g_pool[curg * 192 + j], a);
            curg = g; a = 0.f;
        }
        a += v;
    }
    if (curg >= 0) atomicAdd(&g_pool[curg * 192 + j], a);
}

// ------------------------- final classifier + mean -------------------------
__global__ void k_final(const float* __restrict__ Wc, const float* __restrict__ bc,
                        float* __restrict__ out) {
    int t = threadIdx.x;                          // 384 threads
    int b = t / 48, rem = t % 48, h = rem / 16, c = rem & 15;
    float inv = 1.f / fmaxf(g_cnt[b], 1.f);
    const float* P = g_pool + (b * 3 + h) * 64;
    float dot = bc[c];
#pragma unroll
    for (int k = 0; k < 64; k++) dot += P[k] * inv * Wc[k * 16 + c];
    float sg = 1.f / (1.f + expf(-dot));
#pragma unroll
    for (int off = 8; off; off >>= 1) sg += __shfl_xor_sync(0xffffffffu, sg, off);
    if (c == 0) out[b * 3 + h] = sg * (1.f / 16.f);
}

// ------------------------- launcher -------------------------
extern "C" void kernel_launch(void* const* d_in, const int* in_sizes, int n_in,
                              void* d_out, int out_size) {
    const float* x   = (const float*)d_in[0];
    const int*   src = (const int*)  d_in[1];
    const int*   dst = (const int*)  d_in[2];
    const int*   gid = (const int*)  d_in[3];
    const float* W1  = (const float*)d_in[4];
    const float* b1  = (const float*)d_in[5];
    const float* Wg  = (const float*)d_in[6];
    const float* al  = (const float*)d_in[7];
    const float* ar  = (const float*)d_in[8];
    const float* bg  = (const float*)d_in[9];
    const float* W2  = (const float*)d_in[10];
    const float* b2  = (const float*)d_in[11];
    const float* Wc  = (const float*)d_in[12];
    const float* bc  = (const float*)d_in[13];
    float* out = (float*)d_out;

    float *pxW, *ph1, *pf, *pgat, *pxW2;
    cudaGetSymbolAddress((void**)&pxW,  g_xW);
    cudaGetSymbolAddress((void**)&ph1,  g_h1);
    cudaGetSymbolAddress((void**)&pf,   g_f);
    cudaGetSymbolAddress((void**)&pgat, g_gat);
    cudaGetSymbolAddress((void**)&pxW2, g_xW2);

    constexpr int SM128 = (64 * (128 + 4) + 128 * 64) * 4;   // 66560 B (FFMA mm1)
    cudaFuncSetAttribute(k_gemm<128>, cudaFuncAttributeMaxDynamicSharedMemorySize, SM128);

    // side stream + events for fork-join inside graph capture
    static cudaStream_t s2 = nullptr;
    static cudaEvent_t ev_fork = nullptr, ev_join = nullptr;
    if (!s2) {
        cudaStreamCreateWithFlags(&s2, cudaStreamNonBlocking);
        cudaEventCreateWithFlags(&ev_fork, cudaEventDisableTiming);
        cudaEventCreateWithFlags(&ev_join, cudaEventDisableTiming);
    }

    // fork: mm1 (x @ W1) on side stream
    cudaEventRecord(ev_fork, 0);
    cudaStreamWaitEvent(s2, ev_fork, 0);
    k_gemm<128><<<dim3((cN + 63) / 64, 3, 1), 256, SM128, s2>>>(
        x, 128, W1, 64, (size_t)128 * 64, pxW, 64, (size_t)cN * 64, cN);
    cudaEventRecord(ev_join, s2);

    // main: CSR build
    k_init0<<<(cRN + 255) / 256, 256>>>();
    k_deg<<<(cRE + 255) / 256, 256>>>(src, dst);
    k_norm<<<(cRN + 255) / 256, 256>>>();
    k_scanA<<<SCAN_NB, 256>>>();
    k_scanB<<<1, 256>>>();
    k_scanC<<<(cRN + 255) / 256, 256>>>();
    k_fill<<<(cRE + 255) / 256, 256>>>(src, dst);
    k_cnt<<<(cN + 255) / 256, 256>>>(gid);

    // join: gath1 needs g_xW (s2) + CSR (main)
    cudaStreamWaitEvent(0, ev_join, 0);
    k_gath1<<<(cN + 7) / 8, 256>>>(b1);

    // GAT: f = h1 @ Wg via tf32 mma.sync (fused el/er epilogue)
    k_hmm<192, true><<<dim3((cN + 63) / 64, 3, 3), 128>>>(ph1, Wg, al, ar, pf, cN);
    k_ggat<<<(cN + 7) / 8, 256>>>(bg);

    // layer 2: xW2 = gat @ W2 via tf32 mma.sync
    k_hmm<64, false><<<dim3((cM + 63) / 64, 3, 1), 128>>>(pgat, W2, nullptr, nullptr, pxW2, cM);
    k_gath2<<<(cN + 7) / 8, 256>>>(b2);

    // pooling + classifier
    k_pool<<<(cN + 63) / 64, 192>>>(gid);
    k_final<<<1, 384>>>(Wc, bc, out);
}

// round 11
// speedup vs baseline: 3.6297x; 1.2744x over previous
#include <cuda_runtime.h>
#include <cuda_bf16.h>
#include <cstdint>

// Problem constants (fixed by the reference)
constexpr int cN   = 50000;
constexpr int cE   = 400000;
constexpr int cR   = 3;
constexpr int cH   = 3;
constexpr int cIN  = 128;
constexpr int cHID = 64;
constexpr int cOUT = 64;
constexpr int cC   = 16;
constexpr int cB   = 8;
constexpr int cF2  = cH * cHID;   // 192
constexpr int cM   = cN * cH;     // 150000 rows for conv2
constexpr int cRN  = cR * cN;     // 150000
constexpr int cRE  = cR * cE;     // 1.2M
constexpr int SCAN_NB = (cRN + 1023) / 1024;  // 147

// ------------------------- device scratch (static, no alloc) -------------------------
__device__ int      g_outdeg[cRN];
__device__ int      g_indeg[cRN];
__device__ float    g_ns[cRN];
__device__ float    g_nd[cRN];
__device__ int      g_off[cRN + 1];
__device__ int      g_cursor[cRN];
__device__ int      g_bsum[256];
__device__ int      g_esrc[cRE];
__device__ float    g_xW[cRN * cHID];
__device__ float    g_h1[cN * cHID];
__device__ __nv_bfloat16 g_fh[(size_t)cRN * cF2];       // GAT features, bf16 (57.6 MB, L2-resident)
__device__ float    g_el4[cRN * 4];                     // padded: [idx*4 + h], h<3 (fp32)
__device__ float    g_er4[cRN * 4];
__device__ float    g_gat[cN * cF2];
__device__ __nv_bfloat16 g_xW2h[(size_t)cR * cM * cOUT];// conv2 features, bf16 (57.6 MB)
__device__ float    g_acc2[cM * cOUT];
__device__ float    g_pool[cB * cF2];
__device__ float    g_cnt[cB];

__device__ __forceinline__ float sigmoidf_(float v) { return 1.f / (1.f + __expf(-v)); }

// tf32 round (rna)
__device__ __forceinline__ float tf32c(float x) {
    uint32_t o; asm("cvt.rna.tf32.f32 %0, %1;" : "=r"(o) : "f"(x));
    return __uint_as_float(o);
}
// m16n8k8 tf32 mma, fp32 accumulate (arch-agnostic PTX)
__device__ __forceinline__ void mma8(float* c, uint32_t a0, uint32_t a1, uint32_t a2,
                                     uint32_t a3, uint32_t b0, uint32_t b1) {
    asm volatile("mma.sync.aligned.m16n8k8.row.col.f32.tf32.tf32.f32 "
                 "{%0,%1,%2,%3}, {%4,%5,%6,%7}, {%8,%9}, {%0,%1,%2,%3};"
                 : "+f"(c[0]), "+f"(c[1]), "+f"(c[2]), "+f"(c[3])
                 : "r"(a0), "r"(a1), "r"(a2), "r"(a3), "r"(b0), "r"(b1));
}

// ------------------------- init -------------------------
__global__ void k_init0() {
    int i = blockIdx.x * blockDim.x + threadIdx.x;
    if (i < cRN) { g_outdeg[i] = 0; g_indeg[i] = 0; }
    if (i < cB * cF2) g_pool[i] = 0.f;
    if (i < cB)       g_cnt[i] = 0.f;
}

// ------------------------- degrees -------------------------
__global__ void k_deg(const int* __restrict__ src, const int* __restrict__ dst) {
    int i = blockIdx.x * blockDim.x + threadIdx.x;
    if (i >= cRE) return;
    int r = i / cE;
    atomicAdd(&g_outdeg[r * cN + src[i]], 1);
    atomicAdd(&g_indeg[r * cN + dst[i]], 1);
}
__global__ void k_norm() {
    int i = blockIdx.x * blockDim.x + threadIdx.x;
    if (i >= cRN) return;
    g_ns[i] = rsqrtf(fmaxf((float)g_outdeg[i], 1.f));
    g_nd[i] = rsqrtf(fmaxf((float)g_indeg[i], 1.f));
}

// ------------------------- exclusive scan of indeg -> offsets -------------------------
__global__ void k_scanA() {
    __shared__ int wsum[8];
    int tid = threadIdx.x, lane = tid & 31, wid = tid >> 5;
    int idx0 = blockIdx.x * 1024 + tid * 4;
    int v[4]; int s = 0;
#pragma unroll
    for (int k = 0; k < 4; k++) {
        int i = idx0 + k;
        int x = (i < cRN) ? g_indeg[i] : 0;
        v[k] = s; s += x;
    }
    int incl = s;
#pragma unroll
    for (int o = 1; o < 32; o <<= 1) {
        int t = __shfl_up_sync(0xffffffffu, incl, o);
        if (lane >= o) incl += t;
    }
    int excl = incl - s;
    if (lane == 31) wsum[wid] = incl;
    __syncthreads();
    if (tid == 0) {
        int a = 0;
#pragma unroll
        for (int w = 0; w < 8; w++) { int t = wsum[w]; wsum[w] = a; a += t; }
        g_bsum[blockIdx.x] = a;
    }
    __syncthreads();
    int base = wsum[wid] + excl;
#pragma unroll
    for (int k = 0; k < 4; k++) {
        int i = idx0 + k;
        if (i < cRN) g_off[i] = base + v[k];
    }
}
__global__ void k_scanB() {
    __shared__ int wsum[8];
    int tid = threadIdx.x, lane = tid & 31, wid = tid >> 5;
    int v = (tid < SCAN_NB) ? g_bsum[tid] : 0;
    int incl = v;
#pragma unroll
    for (int o = 1; o < 32; o <<= 1) {
        int t = __shfl_up_sync(0xffffffffu, incl, o);
        if (lane >= o) incl += t;
    }
    if (lane == 31) wsum[wid] = incl;
    __syncthreads();
    if (tid == 0) {
        int a = 0;
#pragma unroll
        for (int w = 0; w < 8; w++) { int t = wsum[w]; wsum[w] = a; a += t; }
    }
    __syncthreads();
    if (tid < SCAN_NB) g_bsum[tid] = wsum[wid] + incl - v;
}
__global__ void k_scanC() {
    int i = blockIdx.x * blockDim.x + threadIdx.x;
    if (i >= cRN) return;
    int o = g_off[i] + g_bsum[i >> 10];
    g_off[i] = o;
    g_cursor[i] = o;
    if (i == 0) g_off[cRN] = cRE;
}
__global__ void k_fill(const int* __restrict__ src, const int* __restrict__ dst) {
    int i = blockIdx.x * blockDim.x + threadIdx.x;
    if (i >= cRE) return;
    int r = i / cE;
    int pos = atomicAdd(&g_cursor[r * cN + dst[i]], 1);
    g_esrc[pos] = src[i];
}

// ------------------------- tf32 mma.sync GEMM (K-blocked) ---------------------------------------
// C[64-row tile, 64 cols @ ct] = A[·, K] @ Bsrc[r][K, LDB] cols [ct*64, ct*64+64)
// 128 threads / 4 warps; warp = 16 rows x 64 cols (8 col tiles of m16n8k8).
// BF: write bf16-packed output. ATT: fused el/er head-dot epilogue (ct == head).
template<int K, int LDB, bool ATT, bool BF>
__global__ void __launch_bounds__(128) k_hmm(
    const float* __restrict__ A,            // [rows, K]
    const float* __restrict__ Bsrc,         // [R, K, LDB]
    const float* __restrict__ al,           // [R, 3, 64] (ATT only)
    const float* __restrict__ ar,
    void* __restrict__ Cout,                // float or bf16 [R, rows, LDB]
    int rows)
{
    __shared__ float sA[64][68];            // (4*gid+tig)%32 -> conflict-free A frags
    __shared__ float sB[64][72];            // (8*tig+gid)%32 -> conflict-free B frags
    __shared__ float sAl[2][64];
    int tid = threadIdx.x, warp = tid >> 5, lane = tid & 31;
    int gid = lane >> 2, tig = lane & 3;
    int r = blockIdx.y, ct = blockIdx.z;
    int n0 = blockIdx.x * 64;

    if (ATT && tid < 64) {
        sAl[0][tid] = __ldg(&al[r * 192 + ct * 64 + tid]);
        sAl[1][tid] = __ldg(&ar[r * 192 + ct * 64 + tid]);
    }

    int r0 = warp * 16;
    float c[8][4];
#pragma unroll
    for (int t = 0; t < 8; t++)
#pragma unroll
        for (int j = 0; j < 4; j++) c[t][j] = 0.f;

    const float* Ab = A + (size_t)n0 * K;
    const float* Bb = Bsrc + (size_t)r * K * LDB + ct * 64;

#pragma unroll
    for (int kb = 0; kb < K; kb += 64) {
        if (kb) __syncthreads();            // protect smem reuse across K blocks
        // load A sub-tile [64 rows][64 k], round to tf32
        for (int i = tid; i < 64 * 16; i += 128) {
            int row = i >> 4, c4 = (i & 15) * 4;
            float4 v = (n0 + row < rows)
                ? __ldg((const float4*)(Ab + (size_t)row * K + kb + c4))
                : make_float4(0.f, 0.f, 0.f, 0.f);
            sA[row][c4]     = tf32c(v.x);
            sA[row][c4 + 1] = tf32c(v.y);
            sA[row][c4 + 2] = tf32c(v.z);
            sA[row][c4 + 3] = tf32c(v.w);
        }
        // load B sub-tile [64 k][64 n], round to tf32
        for (int i = tid; i < 64 * 16; i += 128) {
            int k = i >> 4, c4 = (i & 15) * 4;
            float4 v = __ldg((const float4*)(Bb + (size_t)(kb + k) * LDB + c4));
            sB[k][c4]     = tf32c(v.x);
            sB[k][c4 + 1] = tf32c(v.y);
            sB[k][c4 + 2] = tf32c(v.z);
            sB[k][c4 + 3] = tf32c(v.w);
        }
        __syncthreads();
#pragma unroll
        for (int kt = 0; kt < 8; kt++) {
            int k0 = kt * 8;
            uint32_t a0 = __float_as_uint(sA[r0 + gid][k0 + tig]);
            uint32_t a1 = __float_as_uint(sA[r0 + gid + 8][k0 + tig]);
            uint32_t a2 = __float_as_uint(sA[r0 + gid][k0 + tig + 4]);
            uint32_t a3 = __float_as_uint(sA[r0 + gid + 8][k0 + tig + 4]);
#pragma unroll
            for (int t = 0; t < 8; t++) {
                uint32_t b0 = __float_as_uint(sB[k0 + tig][t * 8 + gid]);
                uint32_t b1 = __float_as_uint(sB[k0 + tig + 4][t * 8 + gid]);
                mma8(c[t], a0, a1, a2, a3, b0, b1);
            }
        }
    }

    int row0 = n0 + r0 + gid, row1 = row0 + 8;
    size_t base = (size_t)r * rows;
#pragma unroll
    for (int t = 0; t < 8; t++) {
        int col = ct * 64 + t * 8 + tig * 2;
        if (BF) {
            __nv_bfloat16* Cb = (__nv_bfloat16*)Cout;
            if (row0 < rows) *(__nv_bfloat162*)(Cb + (base + row0) * LDB + col) =
                __floats2bfloat162_rn(c[t][0], c[t][1]);
            if (row1 < rows) *(__nv_bfloat162*)(Cb + (base + row1) * LDB + col) =
                __floats2bfloat162_rn(c[t][2], c[t][3]);
        } else {
            float* Cf = (float*)Cout;
            if (row0 < rows) *(float2*)(Cf + (base + row0) * LDB + col) = make_float2(c[t][0], c[t][1]);
            if (row1 < rows) *(float2*)(Cf + (base + row1) * LDB + col) = make_float2(c[t][2], c[t][3]);
        }
    }

    if (ATT) {
        float pl0 = 0.f, pl1 = 0.f, pr0 = 0.f, pr1 = 0.f;
#pragma unroll
        for (int t = 0; t < 8; t++) {
            float l0 = sAl[0][t * 8 + tig * 2], l1 = sAl[0][t * 8 + tig * 2 + 1];
            float q0 = sAl[1][t * 8 + tig * 2], q1 = sAl[1][t * 8 + tig * 2 + 1];
            pl0 += c[t][0] * l0 + c[t][1] * l1;
            pl1 += c[t][2] * l0 + c[t][3] * l1;
            pr0 += c[t][0] * q0 + c[t][1] * q1;
            pr1 += c[t][2] * q0 + c[t][3] * q1;
        }
#pragma unroll
        for (int o = 1; o < 4; o <<= 1) {
            pl0 += __shfl_xor_sync(0xffffffffu, pl0, o);
            pl1 += __shfl_xor_sync(0xffffffffu, pl1, o);
            pr0 += __shfl_xor_sync(0xffffffffu, pr0, o);
            pr1 += __shfl_xor_sync(0xffffffffu, pr1, o);
        }
        if (tig == 0) {
            if (row0 < rows) { g_el4[(r * cN + row0) * 4 + ct] = pl0; g_er4[(r * cN + row0) * 4 + ct] = pr0; }
            if (row1 < rows) { g_el4[(r * cN + row1) * 4 + ct] = pl1; g_er4[(r * cN + row1) * 4 + ct] = pr1; }
        }
    }
}

// ------------------------- conv1 gather + L2 normalize (fused) -------------------------
__global__ void __launch_bounds__(256) k_gath1(const float* __restrict__ b1) {
    int gw = blockIdx.x * 8 + (threadIdx.x >> 5);
    int lane = threadIdx.x & 31;
    if (gw >= cN) return;
    int n = gw;
    int p = lane * 2;
    float2 a;
    a.x = b1[p]     + b1[64 + p]     + b1[128 + p];
    a.y = b1[p + 1] + b1[64 + p + 1] + b1[128 + p + 1];
#define G1_BODY(J) { \
    int s_ = __ldg(&g_esrc[J]); \
    float sc_ = __ldg(&g_ns[r * cN + s_]) * nd; \
    float2 v_ = __ldg((const float2*)(g_xW + (size_t)(r * cN + s_) * 64) + lane); \
    a.x += sc_ * v_.x; a.y += sc_ * v_.y; }
#pragma unroll
    for (int r = 0; r < 3; r++) {
        int idx = r * cN + n;
        float nd = g_nd[idx];
        int beg = g_off[idx], end = g_off[idx + 1];
        int j = beg;
        for (; j + 4 <= end; j += 4) { G1_BODY(j) G1_BODY(j + 1) G1_BODY(j + 2) G1_BODY(j + 3) }
        for (; j < end; ++j) { G1_BODY(j) }
    }
#undef G1_BODY
    float ss = a.x * a.x + a.y * a.y;
#pragma unroll
    for (int o = 16; o; o >>= 1) ss += __shfl_xor_sync(0xffffffffu, ss, o);
    float inv = 1.f / fmaxf(sqrtf(ss), 1e-12f);
    float2* outp = (float2*)(g_h1 + (size_t)n * 64) + lane;
    outp->x = a.x * inv; outp->y = a.y * inv;
}

// ------------------------- GAT gather: shift-free softmax + weighted agg + relu -------------------------
__global__ void __launch_bounds__(256) k_ggat(const float* __restrict__ bg) {
    int gw = blockIdx.x * 8 + (threadIdx.x >> 5);
    int lane = threadIdx.x & 31;
    if (gw >= cN) return;
    int n = gw;
    int p = lane * 2;
    float2 acc0, acc1, acc2;
    acc0.x = bg[p]          + bg[192 + p]          + bg[384 + p];
    acc0.y = bg[p + 1]      + bg[192 + p + 1]      + bg[384 + p + 1];
    acc1.x = bg[64 + p]     + bg[256 + p]          + bg[448 + p];
    acc1.y = bg[64 + p + 1] + bg[256 + p + 1]      + bg[448 + p + 1];
    acc2.x = bg[128 + p]    + bg[320 + p]          + bg[512 + p];
    acc2.y = bg[128 + p + 1]+ bg[320 + p + 1]      + bg[512 + p + 1];
#define GG_BODY(J) { \
    int s_ = __ldg(&g_esrc[J]); \
    size_t sb_ = (size_t)(r * cN + s_); \
    float4 el_ = __ldg((const float4*)g_el4 + sb_); \
    float e0_ = el_.x + er.x, e1_ = el_.y + er.y, e2_ = el_.z + er.z; \
    e0_ = e0_ > 0.f ? e0_ : 0.2f * e0_; \
    e1_ = e1_ > 0.f ? e1_ : 0.2f * e1_; \
    e2_ = e2_ > 0.f ? e2_ : 0.2f * e2_; \
    float w0_ = __expf(e0_), w1_ = __expf(e1_), w2_ = __expf(e2_); \
    const __nv_bfloat162* fr_ = (const __nv_bfloat162*)(g_fh + sb_ * 192); \
    float2 f0_ = __bfloat1622float2(__ldg(fr_ + lane)); \
    float2 f1_ = __bfloat1622float2(__ldg(fr_ + 32 + lane)); \
    float2 f2_ = __bfloat1622float2(__ldg(fr_ + 64 + lane)); \
    z0 += w0_; z1 += w1_; z2 += w2_; \
    t0.x += w0_ * f0_.x; t0.y += w0_ * f0_.y; \
    t1.x += w1_ * f1_.x; t1.y += w1_ * f1_.y; \
    t2.x += w2_ * f2_.x; t2.y += w2_ * f2_.y; }
#pragma unroll
    for (int r = 0; r < 3; r++) {
        int idx = r * cN + n;
        float4 er = __ldg((const float4*)g_er4 + idx);
        float z0 = 0.f, z1 = 0.f, z2 = 0.f;
        float2 t0 = {0.f, 0.f}, t1 = {0.f, 0.f}, t2 = {0.f, 0.f};
        int beg = g_off[idx], end = g_off[idx + 1];
        int j = beg;
        for (; j + 4 <= end; j += 4) { GG_BODY(j) GG_BODY(j + 1) GG_BODY(j + 2) GG_BODY(j + 3) }
        for (; j < end; ++j) { GG_BODY(j) }
        float r0 = 1.f / (z0 + 1e-9f), r1 = 1.f / (z1 + 1e-9f), r2 = 1.f / (z2 + 1e-9f);
        acc0.x += t0.x * r0; acc0.y += t0.y * r0;
        acc1.x += t1.x * r1; acc1.y += t1.y * r1;
        acc2.x += t2.x * r2; acc2.y += t2.y * r2;
    }
#undef GG_BODY
    float2* o0 = (float2*)(g_gat + (size_t)n * 192)       + lane;
    float2* o1 = (float2*)(g_gat + (size_t)n * 192 + 64)  + lane;
    float2* o2 = (float2*)(g_gat + (size_t)n * 192 + 128) + lane;
    o0->x = fmaxf(acc0.x, 0.f); o0->y = fmaxf(acc0.y, 0.f);
    o1->x = fmaxf(acc1.x, 0.f); o1->y = fmaxf(acc1.y, 0.f);
    o2->x = fmaxf(acc2.x, 0.f); o2->y = fmaxf(acc2.y, 0.f);
}

// ------------------------- conv2 gather + sigmoid (fused) -------------------------
__global__ void __launch_bounds__(256) k_gath2(const float* __restrict__ b2) {
    int gw = blockIdx.x * 8 + (threadIdx.x >> 5);
    int lane = threadIdx.x & 31;
    if (gw >= cN) return;
    int n = gw;
    int p = lane * 2;
    float bx = b2[p]     + b2[64 + p]     + b2[128 + p];
    float by = b2[p + 1] + b2[64 + p + 1] + b2[128 + p + 1];
    float2 acc0 = {bx, by}, acc1 = {bx, by}, acc2 = {bx, by};
#define G2_BODY(J) { \
    int s_ = __ldg(&g_esrc[J]); \
    float sc_ = __ldg(&g_ns[r * cN + s_]) * nd; \
    const __nv_bfloat162* base_ = (const __nv_bfloat162*)(g_xW2h + ((size_t)r * cM + (size_t)s_ * 3) * 64); \
    float2 f0_ = __bfloat1622float2(__ldg(base_ + lane)); \
    float2 f1_ = __bfloat1622float2(__ldg(base_ + 32 + lane)); \
    float2 f2_ = __bfloat1622float2(__ldg(base_ + 64 + lane)); \
    acc0.x += sc_ * f0_.x; acc0.y += sc_ * f0_.y; \
    acc1.x += sc_ * f1_.x; acc1.y += sc_ * f1_.y; \
    acc2.x += sc_ * f2_.x; acc2.y += sc_ * f2_.y; }
#pragma unroll
    for (int r = 0; r < 3; r++) {
        int idx = r * cN + n;
        float nd = g_nd[idx];
        int beg = g_off[idx], end = g_off[idx + 1];
        int j = beg;
        for (; j + 4 <= end; j += 4) { G2_BODY(j) G2_BODY(j + 1) G2_BODY(j + 2) G2_BODY(j + 3) }
        for (; j < end; ++j) { G2_BODY(j) }
    }
#undef G2_BODY
    float2* o0 = (float2*)(g_acc2 + (size_t)n * 192)       + lane;
    float2* o1 = (float2*)(g_acc2 + (size_t)n * 192 + 64)  + lane;
    float2* o2 = (float2*)(g_acc2 + (size_t)n * 192 + 128) + lane;
    o0->x = sigmoidf_(acc0.x); o0->y = sigmoidf_(acc0.y);
    o1->x = sigmoidf_(acc1.x); o1->y = sigmoidf_(acc1.y);
    o2->x = sigmoidf_(acc2.x); o2->y = sigmoidf_(acc2.y);
}

// ------------------------- node counts per graph -------------------------
__global__ void k_cnt(const int* __restrict__ gid) {
    int i = blockIdx.x * blockDim.x + threadIdx.x;
    if (i >= cN) return;
    int g = gid[i];
    unsigned m = __match_any_sync(__activemask(), g);
    int leader = __ffs(m) - 1;
    if ((threadIdx.x & 31) == leader)
        atomicAdd(&g_cnt[g], (float)__popc(m));
}

// ------------------------- graph pooling (acc2 already sigmoid'd) -------------------------
__global__ void k_pool(const int* __restrict__ gid) {
    int n0 = blockIdx.x * 64;
    int j  = threadIdx.x;                        // 192 threads
    int curg = -1;
    float a = 0.f;
#pragma unroll 1
    for (int m = 0; m < 64; m++) {
        int n = n0 + m;
        if (n >= cN) break;
        int g = __ldg(&gid[n]);
        float v = g_acc2[(size_t)n * 192 + j];
        if (g != curg) {
            if (curg >= 0) atomicAdd(&g_pool[curg * 192 + j], a);
            curg = g; a = 0.f;
        }
        a += v;
    }
    if (curg >= 0) atomicAdd(&g_pool[curg * 192 + j], a);
}

// ------------------------- final classifier + mean -------------------------
__global__ void k_final(const float* __restrict__ Wc, const float* __restrict__ bc,
                        float* __restrict__ out) {
    int t = threadIdx.x;                          // 384 threads
    int b = t / 48, rem = t % 48, h = rem / 16, c = rem & 15;
    float inv = 1.f / fmaxf(g_cnt[b], 1.f);
    const float* P = g_pool + (b * 3 + h) * 64;
    float dot = bc[c];
#pragma unroll
    for (int k = 0; k < 64; k++) dot += P[k] * inv * Wc[k * 16 + c];
    float sg = 1.f / (1.f + expf(-dot));
#pragma unroll
    for (int off = 8; off; off >>= 1) sg += __shfl_xor_sync(0xffffffffu, sg, off);
    if (c == 0) out[b * 3 + h] = sg * (1.f / 16.f);
}

// ------------------------- launcher -------------------------
extern "C" void kernel_launch(void* const* d_in, const int* in_sizes, int n_in,
                              void* d_out, int out_size) {
    const float* x   = (const float*)d_in[0];
    const int*   src = (const int*)  d_in[1];
    const int*   dst = (const int*)  d_in[2];
    const int*   gid = (const int*)  d_in[3];
    const float* W1  = (const float*)d_in[4];
    const float* b1  = (const float*)d_in[5];
    const float* Wg  = (const float*)d_in[6];
    const float* al  = (const float*)d_in[7];
    const float* ar  = (const float*)d_in[8];
    const float* bg  = (const float*)d_in[9];
    const float* W2  = (const float*)d_in[10];
    const float* b2  = (const float*)d_in[11];
    const float* Wc  = (const float*)d_in[12];
    const float* bc  = (const float*)d_in[13];
    float* out = (float*)d_out;

    void *vxW, *vh1, *vfh, *vgat, *vxW2h;
    cudaGetSymbolAddress(&vxW,   g_xW);
    cudaGetSymbolAddress(&vh1,   g_h1);
    cudaGetSymbolAddress(&vfh,   g_fh);
    cudaGetSymbolAddress(&vgat,  g_gat);
    cudaGetSymbolAddress(&vxW2h, g_xW2h);
    const float* ph1  = (const float*)vh1;
    const float* pgat = (const float*)vgat;

    // side stream + events for fork-join inside graph capture
    static cudaStream_t s2 = nullptr;
    static cudaEvent_t ev_fork = nullptr, ev_join = nullptr;
    if (!s2) {
        cudaStreamCreateWithFlags(&s2, cudaStreamNonBlocking);
        cudaEventCreateWithFlags(&ev_fork, cudaEventDisableTiming);
        cudaEventCreateWithFlags(&ev_join, cudaEventDisableTiming);
    }

    // fork: mm1 (x @ W1) via tf32 mma on side stream (fully hidden behind CSR)
    cudaEventRecord(ev_fork, 0);
    cudaStreamWaitEvent(s2, ev_fork, 0);
    k_hmm<128, 64, false, false><<<dim3((cN + 63) / 64, 3, 1), 128, 0, s2>>>(
        x, W1, nullptr, nullptr, vxW, cN);
    cudaEventRecord(ev_join, s2);

    // main: CSR build
    k_init0<<<(cRN + 255) / 256, 256>>>();
    k_deg<<<(cRE + 255) / 256, 256>>>(src, dst);
    k_norm<<<(cRN + 255) / 256, 256>>>();
    k_scanA<<<SCAN_NB, 256>>>();
    k_scanB<<<1, 256>>>();
    k_scanC<<<(cRN + 255) / 256, 256>>>();
    k_fill<<<(cRE + 255) / 256, 256>>>(src, dst);
    k_cnt<<<(cN + 255) / 256, 256>>>(gid);

    // join: gath1 needs g_xW (s2) + CSR (main)
    cudaStreamWaitEvent(0, ev_join, 0);
    k_gath1<<<(cN + 7) / 8, 256>>>(b1);

    // GAT: f = h1 @ Wg via tf32 mma -> bf16 features, fused el/er epilogue
    k_hmm<64, 192, true, true><<<dim3((cN + 63) / 64, 3, 3), 128>>>(ph1, Wg, al, ar, vfh, cN);
    k_ggat<<<(cN + 7) / 8, 256>>>(bg);

    // layer 2: xW2 = gat @ W2 via tf32 mma -> bf16 features
    k_hmm<64, 64, false, true><<<dim3((cM + 63) / 64, 3, 1), 128>>>(pgat, W2, nullptr, nullptr, vxW2h, cM);
    k_gath2<<<(cN + 7) / 8, 256>>>(b2);

    // pooling + classifier
    k_pool<<<(cN + 63) / 64, 192>>>(gid);
    k_final<<<1, 384>>>(Wc, bc, out);
}

// round 12
// speedup vs baseline: 3.6549x; 1.0070x over previous
#include <cuda_runtime.h>
#include <cuda_bf16.h>
#include <cstdint>

// Problem constants (fixed by the reference)
constexpr int cN   = 50000;
constexpr int cE   = 400000;
constexpr int cR   = 3;
constexpr int cH   = 3;
constexpr int cIN  = 128;
constexpr int cHID = 64;
constexpr int cOUT = 64;
constexpr int cC   = 16;
constexpr int cB   = 8;
constexpr int cF2  = cH * cHID;   // 192
constexpr int cM   = cN * cH;     // 150000 rows for conv2
constexpr int cRN  = cR * cN;     // 150000
constexpr int cRE  = cR * cE;     // 1.2M
constexpr int SCAN_NB = (cRN + 1023) / 1024;  // 147

// ------------------------- device scratch (static, no alloc) -------------------------
__device__ int      g_outdeg[cRN];
__device__ int      g_indeg[cRN];
__device__ float    g_ns[cRN];
__device__ float    g_nd[cRN];
__device__ int      g_off[cRN + 1];
__device__ int      g_cursor[cRN];
__device__ int      g_bsum[256];
__device__ int      g_esrc[cRE];
__device__ __nv_bfloat16 g_xWh[cRN * cHID];             // conv1 features, bf16 (19.2 MB)
__device__ float    g_h1[cN * cHID];
__device__ __nv_bfloat16 g_fh[(size_t)cRN * cF2];       // GAT features, bf16 (57.6 MB)
__device__ float    g_el4[cRN * 4];                     // padded: [idx*4 + h], h<3 (fp32)
__device__ float    g_er4[cRN * 4];
__device__ float    g_gat[cN * cF2];
__device__ __nv_bfloat16 g_xW2h[(size_t)cR * cM * cOUT];// conv2 features, bf16 (57.6 MB)
__device__ float    g_acc2[cM * cOUT];
__device__ float    g_pool[cB * cF2];
__device__ float    g_cnt[cB];

__device__ __forceinline__ float sigmoidf_(float v) { return 1.f / (1.f + __expf(-v)); }

// tf32 round (rna)
__device__ __forceinline__ float tf32c(float x) {
    uint32_t o; asm("cvt.rna.tf32.f32 %0, %1;" : "=r"(o) : "f"(x));
    return __uint_as_float(o);
}
// m16n8k8 tf32 mma, fp32 accumulate (arch-agnostic PTX)
__device__ __forceinline__ void mma8(float* c, uint32_t a0, uint32_t a1, uint32_t a2,
                                     uint32_t a3, uint32_t b0, uint32_t b1) {
    asm volatile("mma.sync.aligned.m16n8k8.row.col.f32.tf32.tf32.f32 "
                 "{%0,%1,%2,%3}, {%4,%5,%6,%7}, {%8,%9}, {%0,%1,%2,%3};"
                 : "+f"(c[0]), "+f"(c[1]), "+f"(c[2]), "+f"(c[3])
                 : "r"(a0), "r"(a1), "r"(a2), "r"(a3), "r"(b0), "r"(b1));
}

// ------------------------- init -------------------------
__global__ void k_init0() {
    int i = blockIdx.x * blockDim.x + threadIdx.x;
    if (i < cRN) { g_outdeg[i] = 0; g_indeg[i] = 0; }
    if (i < cB * cF2) g_pool[i] = 0.f;
    if (i < cB)       g_cnt[i] = 0.f;
}

// ------------------------- degrees -------------------------
__global__ void k_deg(const int* __restrict__ src, const int* __restrict__ dst) {
    int i = blockIdx.x * blockDim.x + threadIdx.x;
    if (i >= cRE) return;
    int r = i / cE;
    atomicAdd(&g_outdeg[r * cN + src[i]], 1);
    atomicAdd(&g_indeg[r * cN + dst[i]], 1);
}

// ------------------------- scan A (fused degree->norm) -------------------------
__global__ void k_scanA() {
    __shared__ int wsum[8];
    int tid = threadIdx.x, lane = tid & 31, wid = tid >> 5;
    int idx0 = blockIdx.x * 1024 + tid * 4;
    int v[4]; int s = 0;
#pragma unroll
    for (int k = 0; k < 4; k++) {
        int i = idx0 + k;
        int x = (i < cRN) ? g_indeg[i] : 0;
        if (i < cRN) {
            g_nd[i] = rsqrtf(fmaxf((float)x, 1.f));
            g_ns[i] = rsqrtf(fmaxf((float)g_outdeg[i], 1.f));
        }
        v[k] = s; s += x;
    }
    int incl = s;
#pragma unroll
    for (int o = 1; o < 32; o <<= 1) {
        int t = __shfl_up_sync(0xffffffffu, incl, o);
        if (lane >= o) incl += t;
    }
    int excl = incl - s;
    if (lane == 31) wsum[wid] = incl;
    __syncthreads();
    if (tid == 0) {
        int a = 0;
#pragma unroll
        for (int w = 0; w < 8; w++) { int t = wsum[w]; wsum[w] = a; a += t; }
        g_bsum[blockIdx.x] = a;
    }
    __syncthreads();
    int base = wsum[wid] + excl;
#pragma unroll
    for (int k = 0; k < 4; k++) {
        int i = idx0 + k;
        if (i < cRN) g_off[i] = base + v[k];
    }
}
__global__ void k_scanB() {
    __shared__ int wsum[8];
    int tid = threadIdx.x, lane = tid & 31, wid = tid >> 5;
    int v = (tid < SCAN_NB) ? g_bsum[tid] : 0;
    int incl = v;
#pragma unroll
    for (int o = 1; o < 32; o <<= 1) {
        int t = __shfl_up_sync(0xffffffffu, incl, o);
        if (lane >= o) incl += t;
    }
    if (lane == 31) wsum[wid] = incl;
    __syncthreads();
    if (tid == 0) {
        int a = 0;
#pragma unroll
        for (int w = 0; w < 8; w++) { int t = wsum[w]; wsum[w] = a; a += t; }
    }
    __syncthreads();
    if (tid < SCAN_NB) g_bsum[tid] = wsum[wid] + incl - v;
}
// scanC + node-count fused
__global__ void k_scanC(const int* __restrict__ gid) {
    int i = blockIdx.x * blockDim.x + threadIdx.x;
    if (i >= cRN) return;
    int o = g_off[i] + g_bsum[i >> 10];
    g_off[i] = o;
    g_cursor[i] = o;
    if (i == 0) g_off[cRN] = cRE;
    if (i < cN) {
        int g = gid[i];
        unsigned m = __match_any_sync(__activemask(), g);
        int leader = __ffs(m) - 1;
        if ((threadIdx.x & 31) == leader)
            atomicAdd(&g_cnt[g], (float)__popc(m));
    }
}
__global__ void k_fill(const int* __restrict__ src, const int* __restrict__ dst) {
    int i = blockIdx.x * blockDim.x + threadIdx.x;
    if (i >= cRE) return;
    int r = i / cE;
    int pos = atomicAdd(&g_cursor[r * cN + dst[i]], 1);
    g_esrc[pos] = src[i];
}

// ------------------------- tf32 mma.sync GEMM (K-blocked) ---------------------------------------
// C[64-row tile, 64 cols @ ct] = A[·, K] @ Bsrc[r][K, LDB] cols [ct*64, ct*64+64)
// 128 threads / 4 warps; warp = 16 rows x 64 cols (8 col tiles of m16n8k8).
// BF: write bf16-packed output. ATT: fused el/er head-dot epilogue (ct == head).
template<int K, int LDB, bool ATT, bool BF>
__global__ void __launch_bounds__(128) k_hmm(
    const float* __restrict__ A,            // [rows, K]
    const float* __restrict__ Bsrc,         // [R, K, LDB]
    const float* __restrict__ al,           // [R, 3, 64] (ATT only)
    const float* __restrict__ ar,
    void* __restrict__ Cout,                // float or bf16 [R, rows, LDB]
    int rows)
{
    __shared__ float sA[64][68];            // (4*gid+tig)%32 -> conflict-free A frags
    __shared__ float sB[64][72];            // (8*tig+gid)%32 -> conflict-free B frags
    __shared__ float sAl[2][64];
    int tid = threadIdx.x, warp = tid >> 5, lane = tid & 31;
    int gid = lane >> 2, tig = lane & 3;
    int r = blockIdx.y, ct = blockIdx.z;
    int n0 = blockIdx.x * 64;

    if (ATT && tid < 64) {
        sAl[0][tid] = __ldg(&al[r * 192 + ct * 64 + tid]);
        sAl[1][tid] = __ldg(&ar[r * 192 + ct * 64 + tid]);
    }

    int r0 = warp * 16;
    float c[8][4];
#pragma unroll
    for (int t = 0; t < 8; t++)
#pragma unroll
        for (int j = 0; j < 4; j++) c[t][j] = 0.f;

    const float* Ab = A + (size_t)n0 * K;
    const float* Bb = Bsrc + (size_t)r * K * LDB + ct * 64;

#pragma unroll
    for (int kb = 0; kb < K; kb += 64) {
        if (kb) __syncthreads();            // protect smem reuse across K blocks
        for (int i = tid; i < 64 * 16; i += 128) {
            int row = i >> 4, c4 = (i & 15) * 4;
            float4 v = (n0 + row < rows)
                ? __ldg((const float4*)(Ab + (size_t)row * K + kb + c4))
                : make_float4(0.f, 0.f, 0.f, 0.f);
            sA[row][c4]     = tf32c(v.x);
            sA[row][c4 + 1] = tf32c(v.y);
            sA[row][c4 + 2] = tf32c(v.z);
            sA[row][c4 + 3] = tf32c(v.w);
        }
        for (int i = tid; i < 64 * 16; i += 128) {
            int k = i >> 4, c4 = (i & 15) * 4;
            float4 v = __ldg((const float4*)(Bb + (size_t)(kb + k) * LDB + c4));
            sB[k][c4]     = tf32c(v.x);
            sB[k][c4 + 1] = tf32c(v.y);
            sB[k][c4 + 2] = tf32c(v.z);
            sB[k][c4 + 3] = tf32c(v.w);
        }
        __syncthreads();
#pragma unroll
        for (int kt = 0; kt < 8; kt++) {
            int k0 = kt * 8;
            uint32_t a0 = __float_as_uint(sA[r0 + gid][k0 + tig]);
            uint32_t a1 = __float_as_uint(sA[r0 + gid + 8][k0 + tig]);
            uint32_t a2 = __float_as_uint(sA[r0 + gid][k0 + tig + 4]);
            uint32_t a3 = __float_as_uint(sA[r0 + gid + 8][k0 + tig + 4]);
#pragma unroll
            for (int t = 0; t < 8; t++) {
                uint32_t b0 = __float_as_uint(sB[k0 + tig][t * 8 + gid]);
                uint32_t b1 = __float_as_uint(sB[k0 + tig + 4][t * 8 + gid]);
                mma8(c[t], a0, a1, a2, a3, b0, b1);
            }
        }
    }

    int row0 = n0 + r0 + gid, row1 = row0 + 8;
    size_t base = (size_t)r * rows;
#pragma unroll
    for (int t = 0; t < 8; t++) {
        int col = ct * 64 + t * 8 + tig * 2;
        if (BF) {
            __nv_bfloat16* Cb = (__nv_bfloat16*)Cout;
            if (row0 < rows) *(__nv_bfloat162*)(Cb + (base + row0) * LDB + col) =
                __floats2bfloat162_rn(c[t][0], c[t][1]);
            if (row1 < rows) *(__nv_bfloat162*)(Cb + (base + row1) * LDB + col) =
                __floats2bfloat162_rn(c[t][2], c[t][3]);
        } else {
            float* Cf = (float*)Cout;
            if (row0 < rows) *(float2*)(Cf + (base + row0) * LDB + col) = make_float2(c[t][0], c[t][1]);
            if (row1 < rows) *(float2*)(Cf + (base + row1) * LDB + col) = make_float2(c[t][2], c[t][3]);
        }
    }

    if (ATT) {
        float pl0 = 0.f, pl1 = 0.f, pr0 = 0.f, pr1 = 0.f;
#pragma unroll
        for (int t = 0; t < 8; t++) {
            float l0 = sAl[0][t * 8 + tig * 2], l1 = sAl[0][t * 8 + tig * 2 + 1];
            float q0 = sAl[1][t * 8 + tig * 2], q1 = sAl[1][t * 8 + tig * 2 + 1];
            pl0 += c[t][0] * l0 + c[t][1] * l1;
            pl1 += c[t][2] * l0 + c[t][3] * l1;
            pr0 += c[t][0] * q0 + c[t][1] * q1;
            pr1 += c[t][2] * q0 + c[t][3] * q1;
        }
#pragma unroll
        for (int o = 1; o < 4; o <<= 1) {
            pl0 += __shfl_xor_sync(0xffffffffu, pl0, o);
            pl1 += __shfl_xor_sync(0xffffffffu, pl1, o);
            pr0 += __shfl_xor_sync(0xffffffffu, pr0, o);
            pr1 += __shfl_xor_sync(0xffffffffu, pr1, o);
        }
        if (tig == 0) {
            if (row0 < rows) { g_el4[(r * cN + row0) * 4 + ct] = pl0; g_er4[(r * cN + row0) * 4 + ct] = pr0; }
            if (row1 < rows) { g_el4[(r * cN + row1) * 4 + ct] = pl1; g_er4[(r * cN + row1) * 4 + ct] = pr1; }
        }
    }
}

// ------------------------- conv1 gather + L2 normalize (fused, bf16 features) -------------------------
__global__ void __launch_bounds__(256) k_gath1(const float* __restrict__ b1) {
    int gw = blockIdx.x * 8 + (threadIdx.x >> 5);
    int lane = threadIdx.x & 31;
    if (gw >= cN) return;
    int n = gw;
    int p = lane * 2;
    float2 a;
    a.x = b1[p]     + b1[64 + p]     + b1[128 + p];
    a.y = b1[p + 1] + b1[64 + p + 1] + b1[128 + p + 1];
#define G1_BODY(J) { \
    int s_ = __ldg(&g_esrc[J]); \
    float sc_ = __ldg(&g_ns[r * cN + s_]) * nd; \
    float2 v_ = __bfloat1622float2(__ldg((const __nv_bfloat162*)(g_xWh + (size_t)(r * cN + s_) * 64) + lane)); \
    a.x += sc_ * v_.x; a.y += sc_ * v_.y; }
#pragma unroll
    for (int r = 0; r < 3; r++) {
        int idx = r * cN + n;
        float nd = g_nd[idx];
        int beg = g_off[idx], end = g_off[idx + 1];
        int j = beg;
        for (; j + 4 <= end; j += 4) { G1_BODY(j) G1_BODY(j + 1) G1_BODY(j + 2) G1_BODY(j + 3) }
        for (; j < end; ++j) { G1_BODY(j) }
    }
#undef G1_BODY
    float ss = a.x * a.x + a.y * a.y;
#pragma unroll
    for (int o = 16; o; o >>= 1) ss += __shfl_xor_sync(0xffffffffu, ss, o);
    float inv = 1.f / fmaxf(sqrtf(ss), 1e-12f);
    float2* outp = (float2*)(g_h1 + (size_t)n * 64) + lane;
    outp->x = a.x * inv; outp->y = a.y * inv;
}

// ------------------------- GAT gather: shift-free softmax + weighted agg + relu -------------------------
__global__ void __launch_bounds__(256) k_ggat(const float* __restrict__ bg) {
    int gw = blockIdx.x * 8 + (threadIdx.x >> 5);
    int lane = threadIdx.x & 31;
    if (gw >= cN) return;
    int n = gw;
    int p = lane * 2;
    float2 acc0, acc1, acc2;
    acc0.x = bg[p]          + bg[192 + p]          + bg[384 + p];
    acc0.y = bg[p + 1]      + bg[192 + p + 1]      + bg[384 + p + 1];
    acc1.x = bg[64 + p]     + bg[256 + p]          + bg[448 + p];
    acc1.y = bg[64 + p + 1] + bg[256 + p + 1]      + bg[448 + p + 1];
    acc2.x = bg[128 + p]    + bg[320 + p]          + bg[512 + p];
    acc2.y = bg[128 + p + 1]+ bg[320 + p + 1]      + bg[512 + p + 1];
#define GG_BODY(J) { \
    int s_ = __ldg(&g_esrc[J]); \
    size_t sb_ = (size_t)(r * cN + s_); \
    float4 el_ = __ldg((const float4*)g_el4 + sb_); \
    float e0_ = el_.x + er.x, e1_ = el_.y + er.y, e2_ = el_.z + er.z; \
    e0_ = e0_ > 0.f ? e0_ : 0.2f * e0_; \
    e1_ = e1_ > 0.f ? e1_ : 0.2f * e1_; \
    e2_ = e2_ > 0.f ? e2_ : 0.2f * e2_; \
    float w0_ = __expf(e0_), w1_ = __expf(e1_), w2_ = __expf(e2_); \
    const __nv_bfloat162* fr_ = (const __nv_bfloat162*)(g_fh + sb_ * 192); \
    float2 f0_ = __bfloat1622float2(__ldg(fr_ + lane)); \
    float2 f1_ = __bfloat1622float2(__ldg(fr_ + 32 + lane)); \
    float2 f2_ = __bfloat1622float2(__ldg(fr_ + 64 + lane)); \
    z0 += w0_; z1 += w1_; z2 += w2_; \
    t0.x += w0_ * f0_.x; t0.y += w0_ * f0_.y; \
    t1.x += w1_ * f1_.x; t1.y += w1_ * f1_.y; \
    t2.x += w2_ * f2_.x; t2.y += w2_ * f2_.y; }
#pragma unroll
    for (int r = 0; r < 3; r++) {
        int idx = r * cN + n;
        float4 er = __ldg((const float4*)g_er4 + idx);
        float z0 = 0.f, z1 = 0.f, z2 = 0.f;
        float2 t0 = {0.f, 0.f}, t1 = {0.f, 0.f}, t2 = {0.f, 0.f};
        int beg = g_off[idx], end = g_off[idx + 1];
        int j = beg;
        for (; j + 4 <= end; j += 4) { GG_BODY(j) GG_BODY(j + 1) GG_BODY(j + 2) GG_BODY(j + 3) }
        for (; j < end; ++j) { GG_BODY(j) }
        float r0 = 1.f / (z0 + 1e-9f), r1 = 1.f / (z1 + 1e-9f), r2 = 1.f / (z2 + 1e-9f);
        acc0.x += t0.x * r0; acc0.y += t0.y * r0;
        acc1.x += t1.x * r1; acc1.y += t1.y * r1;
        acc2.x += t2.x * r2; acc2.y += t2.y * r2;
    }
#undef GG_BODY
    float2* o0 = (float2*)(g_gat + (size_t)n * 192)       + lane;
    float2* o1 = (float2*)(g_gat + (size_t)n * 192 + 64)  + lane;
    float2* o2 = (float2*)(g_gat + (size_t)n * 192 + 128) + lane;
    o0->x = fmaxf(acc0.x, 0.f); o0->y = fmaxf(acc0.y, 0.f);
    o1->x = fmaxf(acc1.x, 0.f); o1->y = fmaxf(acc1.y, 0.f);
    o2->x = fmaxf(acc2.x, 0.f); o2->y = fmaxf(acc2.y, 0.f);
}

// ------------------------- conv2 gather + sigmoid (fused) -------------------------
__global__ void __launch_bounds__(256) k_gath2(const float* __restrict__ b2) {
    int gw = blockIdx.x * 8 + (threadIdx.x >> 5);
    int lane = threadIdx.x & 31;
    if (gw >= cN) return;
    int n = gw;
    int p = lane * 2;
    float bx = b2[p]     + b2[64 + p]     + b2[128 + p];
    float by = b2[p + 1] + b2[64 + p + 1] + b2[128 + p + 1];
    float2 acc0 = {bx, by}, acc1 = {bx, by}, acc2 = {bx, by};
#define G2_BODY(J) { \
    int s_ = __ldg(&g_esrc[J]); \
    float sc_ = __ldg(&g_ns[r * cN + s_]) * nd; \
    const __nv_bfloat162* base_ = (const __nv_bfloat162*)(g_xW2h + ((size_t)r * cM + (size_t)s_ * 3) * 64); \
    float2 f0_ = __bfloat1622float2(__ldg(base_ + lane)); \
    float2 f1_ = __bfloat1622float2(__ldg(base_ + 32 + lane)); \
    float2 f2_ = __bfloat1622float2(__ldg(base_ + 64 + lane)); \
    acc0.x += sc_ * f0_.x; acc0.y += sc_ * f0_.y; \
    acc1.x += sc_ * f1_.x; acc1.y += sc_ * f1_.y; \
    acc2.x += sc_ * f2_.x; acc2.y += sc_ * f2_.y; }
#pragma unroll
    for (int r = 0; r < 3; r++) {
        int idx = r * cN + n;
        float nd = g_nd[idx];
        int beg = g_off[idx], end = g_off[idx + 1];
        int j = beg;
        for (; j + 4 <= end; j += 4) { G2_BODY(j) G2_BODY(j + 1) G2_BODY(j + 2) G2_BODY(j + 3) }
        for (; j < end; ++j) { G2_BODY(j) }
    }
#undef G2_BODY
    float2* o0 = (float2*)(g_acc2 + (size_t)n * 192)       + lane;
    float2* o1 = (float2*)(g_acc2 + (size_t)n * 192 + 64)  + lane;
    float2* o2 = (float2*)(g_acc2 + (size_t)n * 192 + 128) + lane;
    o0->x = sigmoidf_(acc0.x); o0->y = sigmoidf_(acc0.y);
    o1->x = sigmoidf_(acc1.x); o1->y = sigmoidf_(acc1.y);
    o2->x = sigmoidf_(acc2.x); o2->y = sigmoidf_(acc2.y);
}

// ------------------------- graph pooling (acc2 already sigmoid'd) -------------------------
__global__ void k_pool(const int* __restrict__ gid) {
    int n0 = blockIdx.x * 64;
    int j  = threadIdx.x;                        // 192 threads
    int curg = -1;
    float a = 0.f;
#pragma unroll 1
    for (int m = 0; m < 64; m++) {
        int n = n0 + m;
        if (n >= cN) break;
        int g = __ldg(&gid[n]);
        float v = g_acc2[(size_t)n * 192 + j];
        if (g != curg) {
            if (curg >= 0) atomicAdd(&g_pool[curg * 192 + j], a);
            curg = g; a = 0.f;
        }
        a += v;
    }
    if (curg >= 0) atomicAdd(&g_pool[curg * 192 + j], a);
}

// ------------------------- final classifier + mean -------------------------
__global__ void k_final(const float* __restrict__ Wc, const float* __restrict__ bc,
                        float* __restrict__ out) {
    int t = threadIdx.x;                          // 384 threads
    int b = t / 48, rem = t % 48, h = rem / 16, c = rem & 15;
    float inv = 1.f / fmaxf(g_cnt[b], 1.f);
    const float* P = g_pool + (b * 3 + h) * 64;
    float dot = bc[c];
#pragma unroll
    for (int k = 0; k < 64; k++) dot += P[k] * inv * Wc[k * 16 + c];
    float sg = 1.f / (1.f + expf(-dot));
#pragma unroll
    for (int off = 8; off; off >>= 1) sg += __shfl_xor_sync(0xffffffffu, sg, off);
    if (c == 0) out[b * 3 + h] = sg * (1.f / 16.f);
}

// ------------------------- launcher -------------------------
extern "C" void kernel_launch(void* const* d_in, const int* in_sizes, int n_in,
                              void* d_out, int out_size) {
    const float* x   = (const float*)d_in[0];
    const int*   src = (const int*)  d_in[1];
    const int*   dst = (const int*)  d_in[2];
    const int*   gid = (const int*)  d_in[3];
    const float* W1  = (const float*)d_in[4];
    const float* b1  = (const float*)d_in[5];
    const float* Wg  = (const float*)d_in[6];
    const float* al  = (const float*)d_in[7];
    const float* ar  = (const float*)d_in[8];
    const float* bg  = (const float*)d_in[9];
    const float* W2  = (const float*)d_in[10];
    const float* b2  = (const float*)d_in[11];
    const float* Wc  = (const float*)d_in[12];
    const float* bc  = (const float*)d_in[13];
    float* out = (float*)d_out;

    void *vxWh, *vh1, *vfh, *vgat, *vxW2h;
    cudaGetSymbolAddress(&vxWh,  g_xWh);
    cudaGetSymbolAddress(&vh1,   g_h1);
    cudaGetSymbolAddress(&vfh,   g_fh);
    cudaGetSymbolAddress(&vgat,  g_gat);
    cudaGetSymbolAddress(&vxW2h, g_xW2h);
    const float* ph1  = (const float*)vh1;
    const float* pgat = (const float*)vgat;

    // side stream + events for fork-join inside graph capture
    static cudaStream_t s2 = nullptr;
    static cudaEvent_t ev_fork = nullptr, ev_join = nullptr;
    if (!s2) {
        cudaStreamCreateWithFlags(&s2, cudaStreamNonBlocking);
        cudaEventCreateWithFlags(&ev_fork, cudaEventDisableTiming);
        cudaEventCreateWithFlags(&ev_join, cudaEventDisableTiming);
    }

    // fork: mm1 (x @ W1) via tf32 mma -> bf16 features, on side stream
    cudaEventRecord(ev_fork, 0);
    cudaStreamWaitEvent(s2, ev_fork, 0);
    k_hmm<128, 64, false, true><<<dim3((cN + 63) / 64, 3, 1), 128, 0, s2>>>(
        x, W1, nullptr, nullptr, vxWh, cN);
    cudaEventRecord(ev_join, s2);

    // main: CSR build (norm fused into scanA, node-count fused into scanC)
    k_init0<<<(cRN + 255) / 256, 256>>>();
    k_deg<<<(cRE + 255) / 256, 256>>>(src, dst);
    k_scanA<<<SCAN_NB, 256>>>();
    k_scanB<<<1, 256>>>();
    k_scanC<<<(cRN + 255) / 256, 256>>>(gid);
    k_fill<<<(cRE + 255) / 256, 256>>>(src, dst);

    // join: gath1 needs g_xWh (s2) + CSR (main)
    cudaStreamWaitEvent(0, ev_join, 0);
    k_gath1<<<(cN + 7) / 8, 256>>>(b1);

    // GAT: f = h1 @ Wg via tf32 mma -> bf16 features, fused el/er epilogue
    k_hmm<64, 192, true, true><<<dim3((cN + 63) / 64, 3, 3), 128>>>(ph1, Wg, al, ar, vfh, cN);
    k_ggat<<<(cN + 7) / 8, 256>>>(bg);

    // layer 2: xW2 = gat @ W2 via tf32 mma -> bf16 features
    k_hmm<64, 64, false, true><<<dim3((cM + 63) / 64, 3, 1), 128>>>(pgat, W2, nullptr, nullptr, vxW2h, cM);
    k_gath2<<<(cN + 7) / 8, 256>>>(b2);

    // pooling + classifier
    k_pool<<<(cN + 63) / 64, 192>>>(gid);
    k_final<<<1, 384>>>(Wc, bc, out);
}